// round 3
// baseline (speedup 1.0000x reference)
#include <cuda_runtime.h>
#include <math.h>

#define Bn   16
#define Tn   1024
#define DIN  384
#define H1n  1024
#define H2n  1024
#define KW   9

// -------- scratch (device globals; no allocation allowed) --------
__device__ float g_X[(size_t)Bn * H1n * Tn];     // mish(GEMM1) transposed: [b][c][t]
__device__ float g_Y[(size_t)Bn * H1n * Tn];     // depthwise-conv output:  [b][c][t]
__device__ float g_dwn[Bn * H1n * KW];           // normalized depthwise weights
__device__ float g_pinv[Bn * H2n];               // 1/||p_w[b,:,o]||
__device__ float g_M[(size_t)Bn * DIN * H1n];    // fused M_b = w2 * pwn^T : [b][d][c]
__device__ float g_bias2[Bn * DIN];              // folded biases per (b,d)

typedef unsigned long long u64;

__device__ __forceinline__ u64 pack2(float lo, float hi) {
    u64 r; asm("mov.b64 %0, {%1,%2};" : "=l"(r) : "f"(lo), "f"(hi)); return r;
}
__device__ __forceinline__ u64 fma2(u64 a, u64 b, u64 c) {
    u64 d; asm("fma.rn.f32x2 %0, %1, %2, %3;" : "=l"(d) : "l"(a), "l"(b), "l"(c)); return d;
}
__device__ __forceinline__ float2 unpack2(u64 v) {
    float2 f; asm("mov.b64 {%0,%1}, %2;" : "=f"(f.x), "=f"(f.y) : "l"(v)); return f;
}

__device__ __forceinline__ float mishf(float x) {
    // softplus = log1p(exp(x)) with overflow guard; matches jax within fp32 noise
    float sp = (x > 20.f) ? x : log1pf(expf(x));
    return x * tanhf(sp);
}

// ---------------------------------------------------------------
// normalized depthwise weights: dwn[b,c,k] = d_w[b,c,k]/||d_w[b,:,k]|| * d_g[b,c]
// ---------------------------------------------------------------
__global__ void k_dwn(const float* __restrict__ dw, const float* __restrict__ dg) {
    int b = blockIdx.x;
    __shared__ float red[256];
    __shared__ float nrm[KW];
    int tid = threadIdx.x;
    float acc[KW];
#pragma unroll
    for (int k = 0; k < KW; k++) acc[k] = 0.f;
    for (int c = tid; c < H1n; c += 256) {
        const float* p = dw + ((size_t)b * H1n + c) * KW;
#pragma unroll
        for (int k = 0; k < KW; k++) { float v = p[k]; acc[k] += v * v; }
    }
    for (int k = 0; k < KW; k++) {
        red[tid] = acc[k];
        __syncthreads();
        for (int s = 128; s > 0; s >>= 1) {
            if (tid < s) red[tid] += red[tid + s];
            __syncthreads();
        }
        if (tid == 0) nrm[k] = fmaxf(sqrtf(red[0]), 1e-12f);
        __syncthreads();
    }
    for (int c = tid; c < H1n; c += 256) {
        float g = dg[b * H1n + c];
        const float* p = dw + ((size_t)b * H1n + c) * KW;
        float* q = g_dwn + ((size_t)b * H1n + c) * KW;
#pragma unroll
        for (int k = 0; k < KW; k++) q[k] = p[k] / nrm[k] * g;
    }
}

// ---------------------------------------------------------------
// g_pinv[b,o] = 1/||p_w[b,:,o]||  (column norms over c)
// ---------------------------------------------------------------
__global__ void k_pinv(const float* __restrict__ pw) {
    int b = blockIdx.y;
    int o = blockIdx.x * 256 + threadIdx.x;
    const float* base = pw + (size_t)b * H1n * H2n + o;
    float acc = 0.f;
#pragma unroll 8
    for (int c = 0; c < H1n; c++) {
        float v = base[(size_t)c * H2n];
        acc += v * v;
    }
    g_pinv[b * H2n + o] = 1.0f / fmaxf(sqrtf(acc), 1e-12f);
}

// ---------------------------------------------------------------
// shared 128x128x8 f32x2 inner product
// ---------------------------------------------------------------
__device__ __forceinline__ void mm_inner(const float As[8][132], const float Bs[8][132],
                                         u64 acc[8][4], int tx, int ty) {
#pragma unroll
    for (int kk = 0; kk < 8; kk++) {
        float4 a0 = *(const float4*)&As[kk][ty * 8];
        float4 a1 = *(const float4*)&As[kk][ty * 8 + 4];
        ulonglong2 bq0 = *(const ulonglong2*)&Bs[kk][tx * 8];
        ulonglong2 bq1 = *(const ulonglong2*)&Bs[kk][tx * 8 + 4];
        float ar[8] = {a0.x, a0.y, a0.z, a0.w, a1.x, a1.y, a1.z, a1.w};
#pragma unroll
        for (int i = 0; i < 8; i++) {
            u64 ad = pack2(ar[i], ar[i]);
            acc[i][0] = fma2(ad, bq0.x, acc[i][0]);
            acc[i][1] = fma2(ad, bq0.y, acc[i][1]);
            acc[i][2] = fma2(ad, bq1.x, acc[i][2]);
            acc[i][3] = fma2(ad, bq1.y, acc[i][3]);
        }
    }
}

// ---------------------------------------------------------------
// GEMM1 + mish, transposed write:  g_X[b][c][t] = mish(in[b,t,:]·w1[c,:] + w1b[c])
// grid (T/128, H1/128, B), 256 thr
// ---------------------------------------------------------------
__global__ void __launch_bounds__(256, 2)
k_gemm1(const float* __restrict__ inp, const float* __restrict__ w1w,
        const float* __restrict__ w1b) {
    __shared__ __align__(16) float As[8][132];
    __shared__ __align__(16) float Bs[8][132];
    int b = blockIdx.z;
    int t0 = blockIdx.x * 128, c0 = blockIdx.y * 128;
    int tid = threadIdx.x;
    int lr = tid >> 1;
    int lk = (tid & 1) << 2;
    int tx = tid & 15, ty = tid >> 4;
    const float* Ag = inp + ((size_t)b * Tn + t0 + lr) * DIN + lk;
    const float* Bg = w1w + (size_t)(c0 + lr) * DIN + lk;
    u64 acc[8][4];
#pragma unroll
    for (int i = 0; i < 8; i++)
#pragma unroll
        for (int j = 0; j < 4; j++) acc[i][j] = 0ull;

    for (int k0 = 0; k0 < DIN; k0 += 8) {
        float4 a = *(const float4*)(Ag + k0);
        float4 bv = *(const float4*)(Bg + k0);
        As[lk + 0][lr] = a.x;  As[lk + 1][lr] = a.y;
        As[lk + 2][lr] = a.z;  As[lk + 3][lr] = a.w;
        Bs[lk + 0][lr] = bv.x; Bs[lk + 1][lr] = bv.y;
        Bs[lk + 2][lr] = bv.z; Bs[lk + 3][lr] = bv.w;
        __syncthreads();
        mm_inner(As, Bs, acc, tx, ty);
        __syncthreads();
    }

    float bb[8];
#pragma unroll
    for (int j = 0; j < 8; j++) bb[j] = w1b[c0 + tx * 8 + j];
    float v[8][8];
#pragma unroll
    for (int i = 0; i < 8; i++)
#pragma unroll
        for (int jp = 0; jp < 4; jp++) {
            float2 f = unpack2(acc[i][jp]);
            v[i][2 * jp]     = mishf(f.x + bb[2 * jp]);
            v[i][2 * jp + 1] = mishf(f.y + bb[2 * jp + 1]);
        }
#pragma unroll
    for (int j = 0; j < 8; j++) {
        size_t base = ((size_t)b * H1n + (c0 + tx * 8 + j)) * Tn + t0 + ty * 8;
        *(float4*)(g_X + base)     = make_float4(v[0][j], v[1][j], v[2][j], v[3][j]);
        *(float4*)(g_X + base + 4) = make_float4(v[4][j], v[5][j], v[6][j], v[7][j]);
    }
}

// ---------------------------------------------------------------
// depthwise conv along t:  g_Y[b,c,t] = T * sum_k g_X[b,c,t+k-4] * dwn[b,c,k]
// (d_b folded into g_bias2)  grid B*H1, 256 thr
// ---------------------------------------------------------------
__global__ void k_conv() {
    int bc = blockIdx.x;                       // b*H1 + c
    __shared__ float xs[Tn + 8];
    const float* x = g_X + (size_t)bc * Tn;
    int tid = threadIdx.x;
    for (int i = tid; i < Tn; i += 256) xs[i + 4] = x[i];
    if (tid < 4) { xs[tid] = 0.f; xs[Tn + 4 + tid] = 0.f; }
    float w[KW];
    const float* wp = g_dwn + (size_t)bc * KW;
#pragma unroll
    for (int k = 0; k < KW; k++) w[k] = wp[k];
    __syncthreads();
    float* y = g_Y + (size_t)bc * Tn;
    for (int t = tid; t < Tn; t += 256) {
        float s = 0.f;
#pragma unroll
        for (int k = 0; k < KW; k++) s += xs[t + k] * w[k];
        y[t] = s * (float)Tn;
    }
}

// ---------------------------------------------------------------
// M_b[d,c] = p_g[b,c] * sum_o (w2[d,o]*pinv[b,o]) * p_w[b,c,o]
// grid (DIN/128, H1/128, B)
// ---------------------------------------------------------------
__global__ void __launch_bounds__(256, 2)
k_gemmC(const float* __restrict__ w2w, const float* __restrict__ pw,
        const float* __restrict__ pg) {
    __shared__ __align__(16) float As[8][132];
    __shared__ __align__(16) float Bs[8][132];
    int b = blockIdx.z;
    int d0 = blockIdx.x * 128, c0 = blockIdx.y * 128;
    int tid = threadIdx.x;
    int lr = tid >> 1;
    int lk = (tid & 1) << 2;
    int tx = tid & 15, ty = tid >> 4;
    const float* Ag = w2w + (size_t)(d0 + lr) * H2n + lk;
    const float* Bg = pw + (size_t)b * H1n * H2n + (size_t)(c0 + lr) * H2n + lk;
    const float* pv = g_pinv + b * H2n + lk;
    u64 acc[8][4];
#pragma unroll
    for (int i = 0; i < 8; i++)
#pragma unroll
        for (int j = 0; j < 4; j++) acc[i][j] = 0ull;

    for (int k0 = 0; k0 < H2n; k0 += 8) {
        float4 a = *(const float4*)(Ag + k0);
        float4 s = *(const float4*)(pv + k0);
        float4 bv = *(const float4*)(Bg + k0);
        As[lk + 0][lr] = a.x * s.x;  As[lk + 1][lr] = a.y * s.y;
        As[lk + 2][lr] = a.z * s.z;  As[lk + 3][lr] = a.w * s.w;
        Bs[lk + 0][lr] = bv.x; Bs[lk + 1][lr] = bv.y;
        Bs[lk + 2][lr] = bv.z; Bs[lk + 3][lr] = bv.w;
        __syncthreads();
        mm_inner(As, Bs, acc, tx, ty);
        __syncthreads();
    }

    float pgv[8];
#pragma unroll
    for (int j = 0; j < 8; j++) pgv[j] = pg[b * H1n + c0 + tx * 8 + j];
#pragma unroll
    for (int i = 0; i < 8; i++) {
        float w[8];
#pragma unroll
        for (int jp = 0; jp < 4; jp++) {
            float2 f = unpack2(acc[i][jp]);
            w[2 * jp]     = f.x * pgv[2 * jp];
            w[2 * jp + 1] = f.y * pgv[2 * jp + 1];
        }
        size_t base = ((size_t)b * DIN + d0 + ty * 8 + i) * H1n + c0 + tx * 8;
        *(float4*)(g_M + base)     = make_float4(w[0], w[1], w[2], w[3]);
        *(float4*)(g_M + base + 4) = make_float4(w[4], w[5], w[6], w[7]);
    }
}

// ---------------------------------------------------------------
// bias2[b,d] = sum_c M[b,d,c]*d_b[b,c] + sum_o w2[d,o]*p_b[b,o] + w2b[d]
// grid (DIN, B), 256 thr
// ---------------------------------------------------------------
__global__ void k_bias2(const float* __restrict__ db, const float* __restrict__ w2w,
                        const float* __restrict__ pb, const float* __restrict__ w2b) {
    int d = blockIdx.x, b = blockIdx.y;
    int tid = threadIdx.x;
    const float* Mrow = g_M + ((size_t)b * DIN + d) * H1n;
    const float* dbp = db + b * H1n;
    float acc = 0.f;
    for (int c = tid; c < H1n; c += 256) acc += Mrow[c] * dbp[c];
    const float* w2r = w2w + (size_t)d * H2n;
    const float* pbp = pb + b * H2n;
    for (int o = tid; o < H2n; o += 256) acc += w2r[o] * pbp[o];
    __shared__ float red[256];
    red[tid] = acc;
    __syncthreads();
    for (int s = 128; s > 0; s >>= 1) {
        if (tid < s) red[tid] += red[tid + s];
        __syncthreads();
    }
    if (tid == 0) g_bias2[b * DIN + d] = red[0] + w2b[d];
}

// ---------------------------------------------------------------
// out[b,t,d] = in[b,t,d] + bias2[b,d] + sum_c M[b,d,c]*Y[b,c,t]
// grid (T/128, DIN/128, B)
// ---------------------------------------------------------------
__global__ void __launch_bounds__(256, 2)
k_gemmE(const float* __restrict__ inp, float* __restrict__ out) {
    __shared__ __align__(16) float As[8][132];
    __shared__ __align__(16) float Bs[8][132];
    int b = blockIdx.z;
    int t0 = blockIdx.x * 128, d0 = blockIdx.y * 128;
    int tid = threadIdx.x;
    int akk = tid >> 5;              // 0..7  (k within tile)
    int ati = (tid & 31) << 2;       // 0..124 (t within tile)
    int lr = tid >> 1;
    int lk = (tid & 1) << 2;
    int tx = tid & 15, ty = tid >> 4;
    const float* Ag = g_Y + ((size_t)b * H1n + akk) * Tn + t0 + ati;
    const float* Bg = g_M + ((size_t)b * DIN + d0 + lr) * H1n + lk;
    u64 acc[8][4];
#pragma unroll
    for (int i = 0; i < 8; i++)
#pragma unroll
        for (int j = 0; j < 4; j++) acc[i][j] = 0ull;

    for (int k0 = 0; k0 < H1n; k0 += 8) {
        float4 a = *(const float4*)(Ag + (size_t)k0 * Tn);
        float4 bv = *(const float4*)(Bg + k0);
        *(float4*)&As[akk][ati] = a;               // Y already [c][t]: no transpose
        Bs[lk + 0][lr] = bv.x; Bs[lk + 1][lr] = bv.y;
        Bs[lk + 2][lr] = bv.z; Bs[lk + 3][lr] = bv.w;
        __syncthreads();
        mm_inner(As, Bs, acc, tx, ty);
        __syncthreads();
    }

    float bb[8];
#pragma unroll
    for (int j = 0; j < 8; j++) bb[j] = g_bias2[b * DIN + d0 + tx * 8 + j];
#pragma unroll
    for (int i = 0; i < 8; i++) {
        int t = t0 + ty * 8 + i;
        size_t base = ((size_t)b * Tn + t) * DIN + d0 + tx * 8;
        float4 r0 = *(const float4*)(inp + base);
        float4 r1 = *(const float4*)(inp + base + 4);
        float2 f0 = unpack2(acc[i][0]);
        float2 f1 = unpack2(acc[i][1]);
        float2 f2 = unpack2(acc[i][2]);
        float2 f3 = unpack2(acc[i][3]);
        float4 o0 = make_float4(f0.x + bb[0] + r0.x, f0.y + bb[1] + r0.y,
                                f1.x + bb[2] + r0.z, f1.y + bb[3] + r0.w);
        float4 o1 = make_float4(f2.x + bb[4] + r1.x, f2.y + bb[5] + r1.y,
                                f3.x + bb[6] + r1.z, f3.y + bb[7] + r1.w);
        *(float4*)(out + base)     = o0;
        *(float4*)(out + base + 4) = o1;
    }
}

// ---------------------------------------------------------------
extern "C" void kernel_launch(void* const* d_in, const int* in_sizes, int n_in,
                              void* d_out, int out_size) {
    const float* inp = (const float*)d_in[0];   // [B,T,DIN]
    const float* dw  = (const float*)d_in[1];   // [B,H1,1,K]
    const float* dg  = (const float*)d_in[2];   // [B,H1]
    const float* db  = (const float*)d_in[3];   // [B,H1]
    const float* pw  = (const float*)d_in[4];   // [B,H1,H2,1]
    const float* pg  = (const float*)d_in[5];   // [B,H1]
    const float* pb  = (const float*)d_in[6];   // [B,H2]
    const float* w1w = (const float*)d_in[7];   // [H1,DIN]
    const float* w1b = (const float*)d_in[8];   // [H1]
    const float* w2w = (const float*)d_in[9];   // [DIN,H2]
    const float* w2b = (const float*)d_in[10];  // [DIN]
    float* out = (float*)d_out;                 // [B,T,DIN]
    (void)in_sizes; (void)n_in; (void)out_size;

    k_dwn<<<Bn, 256>>>(dw, dg);
    k_pinv<<<dim3(H2n / 256, Bn), 256>>>(pw);
    k_gemm1<<<dim3(Tn / 128, H1n / 128, Bn), 256>>>(inp, w1w, w1b);
    k_conv<<<Bn * H1n, 256>>>();
    k_gemmC<<<dim3(DIN / 128, H1n / 128, Bn), 256>>>(w2w, pw, pg);
    k_bias2<<<dim3(DIN, Bn), 256>>>(db, w2w, pb, w2b);
    k_gemmE<<<dim3(Tn / 128, DIN / 128, Bn), 256>>>(inp, out);
}

// round 7
// speedup vs baseline: 1.9781x; 1.9781x over previous
#include <cuda_runtime.h>
#include <cuda_bf16.h>
#include <math.h>
#include <stdint.h>

#define Bn   16
#define Tn   1024
#define DIN  384
#define H1n  1024
#define H2n  1024
#define KW   9

typedef __nv_bfloat16 bf16;

// -------- persistent scratch (device globals; referenced ONLY in device code) ----
__device__ float g_X[(size_t)Bn * Tn * H1n];        // mish(GEMM1): [b][t][c] fp32
__device__ bf16  g_Yh[(size_t)Bn * Tn * H1n];       // conv out hi: [b][t][c]
__device__ bf16  g_Yl[(size_t)Bn * Tn * H1n];       // conv out lo
__device__ bf16  g_ih[(size_t)Bn * Tn * DIN];       // input planes [b][t][k]
__device__ bf16  g_il[(size_t)Bn * Tn * DIN];
__device__ bf16  g_w1h[(size_t)H1n * DIN];          // w1 planes [c][k]
__device__ bf16  g_w1l[(size_t)H1n * DIN];
__device__ bf16  g_pwh[(size_t)Bn * H1n * H2n];     // pw*pinv planes [b][c][o]
__device__ bf16  g_pwl[(size_t)Bn * H1n * H2n];
__device__ bf16  g_w2h[(size_t)DIN * H2n];          // w2 planes [d][o]
__device__ bf16  g_w2l[(size_t)DIN * H2n];
__device__ bf16  g_Mh[(size_t)Bn * DIN * H1n];      // M planes [b][d][c]
__device__ bf16  g_Ml[(size_t)Bn * DIN * H1n];
__device__ float g_dwn[Bn * H1n * KW];
__device__ float g_pinv[Bn * H2n];
__device__ float g_bias2[Bn * DIN];

// ================= base-family PTX helpers =================
__device__ __forceinline__ uint32_t smem_to_u32(const void* p) {
    uint32_t a;
    asm("{ .reg .u64 t; cvta.to.shared.u64 t, %1; cvt.u32.u64 %0, t; }" : "=r"(a) : "l"(p));
    return a;
}
__device__ __forceinline__ void cp16(uint32_t dst, const void* src) {
    asm volatile("cp.async.cg.shared.global [%0], [%1], 16;" :: "r"(dst), "l"(src));
}
__device__ __forceinline__ void cp_commit() {
    asm volatile("cp.async.commit_group;" ::: "memory");
}
__device__ __forceinline__ void mma_bf16(float (&c)[4], const uint32_t (&a)[4],
                                         const uint32_t (&b)[2]) {
    asm volatile(
        "mma.sync.aligned.m16n8k16.row.col.f32.bf16.bf16.f32 "
        "{%0,%1,%2,%3}, {%4,%5,%6,%7}, {%8,%9}, {%0,%1,%2,%3};"
        : "+f"(c[0]), "+f"(c[1]), "+f"(c[2]), "+f"(c[3])
        : "r"(a[0]), "r"(a[1]), "r"(a[2]), "r"(a[3]), "r"(b[0]), "r"(b[1]));
}

// ================= GEMM tile geometry =================
// CTA tile 128x128, K-tile 16 bf16, 2-stage cp.async pipeline, STATIC smem.
// Rows padded to 48B (12 words): frag LDS banks (12g+tig) mod 32 all distinct.
#define PLANE_B 6144u            // 128 rows * 48 B
#define STAGE_B (4u * PLANE_B)   // Ah, Al, Bh, Bl = 24576
#define GSMEM   (2u * STAGE_B)   // 49152 = static smem limit, no opt-in needed

__device__ __forceinline__ void load_stage(uint32_t sb, int buf,
        const bf16* __restrict__ Ah, const bf16* __restrict__ Al, int lda,
        const bf16* __restrict__ Bh, const bf16* __restrict__ Bl, int ldb,
        int k0, int tid) {
    uint32_t base = sb + (uint32_t)buf * STAGE_B;
    int r = tid >> 1, q = tid & 1;          // row 0..127, 16B chunk 0..1
    uint32_t d = base + r * 48 + q * 16;
    size_t ga = (size_t)r * lda + k0 + q * 8;
    size_t gb = (size_t)r * ldb + k0 + q * 8;
    cp16(d,               Ah + ga);
    cp16(d + PLANE_B,     Al + ga);
    cp16(d + 2 * PLANE_B, Bh + gb);
    cp16(d + 3 * PLANE_B, Bl + gb);
}

__device__ __forceinline__ void compute_stage(const char* smem, int buf,
                                              int wm, int wn, int lane,
                                              float acc[4][4][4]) {
    const uint32_t* Ah32 = (const uint32_t*)(smem + (size_t)buf * STAGE_B);
    const uint32_t* Al32 = Ah32 + PLANE_B / 4;
    const uint32_t* Bh32 = Ah32 + 2 * (PLANE_B / 4);
    const uint32_t* Bl32 = Ah32 + 3 * (PLANE_B / 4);
    int g = lane >> 2, tig = lane & 3;
    int ar = (wm * 64 + g) * 12 + tig;
    int br = (wn * 32 + g) * 12 + tig;
    uint32_t ah[4][4], al[4][4], bh[4][2], bl[4][2];
#pragma unroll
    for (int mt = 0; mt < 4; mt++) {
        int base = ar + mt * 192;                    // 16 rows * 12 words
        ah[mt][0] = Ah32[base];      ah[mt][1] = Ah32[base + 96];
        ah[mt][2] = Ah32[base + 4];  ah[mt][3] = Ah32[base + 100];
        al[mt][0] = Al32[base];      al[mt][1] = Al32[base + 96];
        al[mt][2] = Al32[base + 4];  al[mt][3] = Al32[base + 100];
    }
#pragma unroll
    for (int nt = 0; nt < 4; nt++) {
        int base = br + nt * 96;                     // 8 rows * 12 words
        bh[nt][0] = Bh32[base];  bh[nt][1] = Bh32[base + 4];
        bl[nt][0] = Bl32[base];  bl[nt][1] = Bl32[base + 4];
    }
#pragma unroll
    for (int mt = 0; mt < 4; mt++)
#pragma unroll
        for (int nt = 0; nt < 4; nt++) {
            mma_bf16(acc[mt][nt], ah[mt], bh[nt]);
            mma_bf16(acc[mt][nt], ah[mt], bl[nt]);
            mma_bf16(acc[mt][nt], al[mt], bh[nt]);
        }
}

__device__ __forceinline__ void gemm_main(const char* smem, uint32_t sb,
        const bf16* Ah, const bf16* Al, int lda,
        const bf16* Bh, const bf16* Bl, int ldb,
        int kiters, float acc[4][4][4], int tid) {
    int wid = tid >> 5, lane = tid & 31, wm = wid & 1, wn = wid >> 1;
#pragma unroll
    for (int i = 0; i < 4; i++)
#pragma unroll
        for (int j = 0; j < 4; j++)
#pragma unroll
            for (int k = 0; k < 4; k++) acc[i][j][k] = 0.f;

    load_stage(sb, 0, Ah, Al, lda, Bh, Bl, ldb, 0, tid);
    cp_commit();
    for (int it = 0; it < kiters; it++) {
        if (it + 1 < kiters) {
            load_stage(sb, (it + 1) & 1, Ah, Al, lda, Bh, Bl, ldb, (it + 1) * 16, tid);
            cp_commit();
            asm volatile("cp.async.wait_group 1;" ::: "memory");
        } else {
            asm volatile("cp.async.wait_group 0;" ::: "memory");
        }
        __syncthreads();
        compute_stage(smem, it & 1, wm, wn, lane, acc);
        __syncthreads();
    }
}

// mish(x) = x*tanh(softplus(x)) = x*(u^2+2u)/(u^2+2u+2), u=e^x  (exact algebra)
__device__ __forceinline__ float mishf(float x) {
    if (x > 15.f) return x;
    float u = expf(x);
    float t = u * (u + 2.f);
    return x * __fdividef(t, t + 2.f);
}
__device__ __forceinline__ void split_store(bf16* hi, bf16* lo, size_t i, float v) {
    bf16 h = __float2bfloat16(v);
    hi[i] = h;
    lo[i] = __float2bfloat16(v - __bfloat162float(h));
}

// ---------------------------------------------------------------
// GEMM1: D[c,t] = sum_k w1[c,k]*in[b,t,k]; X[b][t][c] = mish(D + w1b[c])
// grid (H1/128, T/128, B), 256 thr
// ---------------------------------------------------------------
__global__ void __launch_bounds__(256)
k_mm1(const float* __restrict__ w1b) {
    __shared__ char smem[GSMEM];
    uint32_t sb = smem_to_u32(smem);
    int tid = threadIdx.x;
    int b = blockIdx.z, c0 = blockIdx.x * 128, t0 = blockIdx.y * 128;
    float acc[4][4][4];
    gemm_main(smem, sb,
              g_w1h + (size_t)c0 * DIN, g_w1l + (size_t)c0 * DIN, DIN,
              g_ih + ((size_t)b * Tn + t0) * DIN, g_il + ((size_t)b * Tn + t0) * DIN, DIN,
              DIN / 16, acc, tid);
    int wid = tid >> 5, lane = tid & 31, wm = wid & 1, wn = wid >> 1;
    int g = lane >> 2, tig = lane & 3;
#pragma unroll
    for (int mt = 0; mt < 4; mt++) {
        int c = c0 + wm * 64 + mt * 16 + g;
        float b0 = w1b[c], b1 = w1b[c + 8];
#pragma unroll
        for (int nt = 0; nt < 4; nt++) {
            int t = t0 + wn * 32 + nt * 8 + tig * 2;
            size_t r0 = ((size_t)b * Tn + t) * H1n;
            size_t r1 = r0 + H1n;
            g_X[r0 + c]     = mishf(acc[mt][nt][0] + b0);
            g_X[r1 + c]     = mishf(acc[mt][nt][1] + b0);
            g_X[r0 + c + 8] = mishf(acc[mt][nt][2] + b1);
            g_X[r1 + c + 8] = mishf(acc[mt][nt][3] + b1);
        }
    }
}

// ---------------------------------------------------------------
// GEMMC: D[c,d] = sum_o pwn[b,c,o]*w2[d,o]; M[b][d][c] = D*pg[b,c] (hi/lo planes)
// grid (H1/128, DIN/128, B)
// ---------------------------------------------------------------
__global__ void __launch_bounds__(256)
k_mmC(const float* __restrict__ pg) {
    __shared__ char smem[GSMEM];
    uint32_t sb = smem_to_u32(smem);
    int tid = threadIdx.x;
    int b = blockIdx.z, c0 = blockIdx.x * 128, d0 = blockIdx.y * 128;
    float acc[4][4][4];
    gemm_main(smem, sb,
              g_pwh + ((size_t)b * H1n + c0) * H2n, g_pwl + ((size_t)b * H1n + c0) * H2n, H2n,
              g_w2h + (size_t)d0 * H2n, g_w2l + (size_t)d0 * H2n, H2n,
              H2n / 16, acc, tid);
    int wid = tid >> 5, lane = tid & 31, wm = wid & 1, wn = wid >> 1;
    int g = lane >> 2, tig = lane & 3;
#pragma unroll
    for (int mt = 0; mt < 4; mt++) {
        int c = c0 + wm * 64 + mt * 16 + g;
        float p0 = pg[b * H1n + c], p1 = pg[b * H1n + c + 8];
#pragma unroll
        for (int nt = 0; nt < 4; nt++) {
            int d = d0 + wn * 32 + nt * 8 + tig * 2;
            size_t r0 = ((size_t)b * DIN + d) * H1n;
            size_t r1 = r0 + H1n;
            split_store(g_Mh, g_Ml, r0 + c,     acc[mt][nt][0] * p0);
            split_store(g_Mh, g_Ml, r1 + c,     acc[mt][nt][1] * p0);
            split_store(g_Mh, g_Ml, r0 + c + 8, acc[mt][nt][2] * p1);
            split_store(g_Mh, g_Ml, r1 + c + 8, acc[mt][nt][3] * p1);
        }
    }
}

// ---------------------------------------------------------------
// GEMME: D[d,t] = sum_c M[b,d,c]*Y[b,t,c]; out = D + bias2 + residual
// grid (DIN/128, T/128, B)
// ---------------------------------------------------------------
__global__ void __launch_bounds__(256)
k_mmE(const float* __restrict__ inp, float* __restrict__ out) {
    __shared__ char smem[GSMEM];
    uint32_t sb = smem_to_u32(smem);
    int tid = threadIdx.x;
    int b = blockIdx.z, d0 = blockIdx.x * 128, t0 = blockIdx.y * 128;
    float acc[4][4][4];
    gemm_main(smem, sb,
              g_Mh + ((size_t)b * DIN + d0) * H1n, g_Ml + ((size_t)b * DIN + d0) * H1n, H1n,
              g_Yh + ((size_t)b * Tn + t0) * H1n, g_Yl + ((size_t)b * Tn + t0) * H1n, H1n,
              H1n / 16, acc, tid);
    int wid = tid >> 5, lane = tid & 31, wm = wid & 1, wn = wid >> 1;
    int g = lane >> 2, tig = lane & 3;
#pragma unroll
    for (int mt = 0; mt < 4; mt++) {
        int d = d0 + wm * 64 + mt * 16 + g;
        float b0 = g_bias2[b * DIN + d], b1 = g_bias2[b * DIN + d + 8];
#pragma unroll
        for (int nt = 0; nt < 4; nt++) {
            int t = t0 + wn * 32 + nt * 8 + tig * 2;
            size_t r0 = ((size_t)b * Tn + t) * DIN;
            size_t r1 = r0 + DIN;
            out[r0 + d]     = acc[mt][nt][0] + b0 + inp[r0 + d];
            out[r1 + d]     = acc[mt][nt][1] + b0 + inp[r1 + d];
            out[r0 + d + 8] = acc[mt][nt][2] + b1 + inp[r0 + d + 8];
            out[r1 + d + 8] = acc[mt][nt][3] + b1 + inp[r1 + d + 8];
        }
    }
}

// ---------------------------------------------------------------
// dedicated convert kernels — device globals referenced ONLY in device code
// ---------------------------------------------------------------
__global__ void k_cvt_inp(const float* __restrict__ s) {
    size_t i = (size_t)blockIdx.x * 256 + threadIdx.x;   // n4 = Bn*Tn*DIN/4 exact multiple
    float4 v = ((const float4*)s)[i];
    size_t o = i * 4;
    split_store(g_ih, g_il, o + 0, v.x);
    split_store(g_ih, g_il, o + 1, v.y);
    split_store(g_ih, g_il, o + 2, v.z);
    split_store(g_ih, g_il, o + 3, v.w);
}
__global__ void k_cvt_w1(const float* __restrict__ s) {
    size_t i = (size_t)blockIdx.x * 256 + threadIdx.x;
    float4 v = ((const float4*)s)[i];
    size_t o = i * 4;
    split_store(g_w1h, g_w1l, o + 0, v.x);
    split_store(g_w1h, g_w1l, o + 1, v.y);
    split_store(g_w1h, g_w1l, o + 2, v.z);
    split_store(g_w1h, g_w1l, o + 3, v.w);
}
__global__ void k_cvt_w2(const float* __restrict__ s) {
    size_t i = (size_t)blockIdx.x * 256 + threadIdx.x;
    float4 v = ((const float4*)s)[i];
    size_t o = i * 4;
    split_store(g_w2h, g_w2l, o + 0, v.x);
    split_store(g_w2h, g_w2l, o + 1, v.y);
    split_store(g_w2h, g_w2l, o + 2, v.z);
    split_store(g_w2h, g_w2l, o + 3, v.w);
}

// pw * pinv[b,o] -> hi/lo planes
__global__ void k_cvt_pw(const float* __restrict__ pw) {
    size_t i = (size_t)blockIdx.x * 256 + threadIdx.x;   // n4 = 4M exactly
    size_t idx = i * 4;
    int o = (int)(idx & (H2n - 1));
    int b = (int)(idx >> 20);
    float4 v = ((const float4*)pw)[i];
    float4 sc = *(const float4*)(g_pinv + b * H2n + o);
    split_store(g_pwh, g_pwl, idx + 0, v.x * sc.x);
    split_store(g_pwh, g_pwl, idx + 1, v.y * sc.y);
    split_store(g_pwh, g_pwl, idx + 2, v.z * sc.z);
    split_store(g_pwh, g_pwl, idx + 3, v.w * sc.w);
}

// ---------------------------------------------------------------
// normalized depthwise weights
// ---------------------------------------------------------------
__global__ void k_dwn(const float* __restrict__ dw, const float* __restrict__ dg) {
    int b = blockIdx.x;
    __shared__ float red[256];
    __shared__ float nrm[KW];
    int tid = threadIdx.x;
    float acc[KW];
#pragma unroll
    for (int k = 0; k < KW; k++) acc[k] = 0.f;
    for (int c = tid; c < H1n; c += 256) {
        const float* p = dw + ((size_t)b * H1n + c) * KW;
#pragma unroll
        for (int k = 0; k < KW; k++) { float v = p[k]; acc[k] += v * v; }
    }
    for (int k = 0; k < KW; k++) {
        red[tid] = acc[k];
        __syncthreads();
        for (int s = 128; s > 0; s >>= 1) {
            if (tid < s) red[tid] += red[tid + s];
            __syncthreads();
        }
        if (tid == 0) nrm[k] = fmaxf(sqrtf(red[0]), 1e-12f);
        __syncthreads();
    }
    for (int c = tid; c < H1n; c += 256) {
        float g = dg[b * H1n + c];
        const float* p = dw + ((size_t)b * H1n + c) * KW;
        float* q = g_dwn + ((size_t)b * H1n + c) * KW;
#pragma unroll
        for (int k = 0; k < KW; k++) q[k] = p[k] / nrm[k] * g;
    }
}

// ---------------------------------------------------------------
// g_pinv[b,o] = 1/||p_w[b,:,o]||
// ---------------------------------------------------------------
__global__ void k_pinv(const float* __restrict__ pw) {
    int b = blockIdx.y;
    int o = blockIdx.x * 256 + threadIdx.x;
    const float* base = pw + (size_t)b * H1n * H2n + o;
    float acc = 0.f;
#pragma unroll 8
    for (int c = 0; c < H1n; c++) {
        float v = base[(size_t)c * H2n];
        acc += v * v;
    }
    g_pinv[b * H2n + o] = 1.0f / fmaxf(sqrtf(acc), 1e-12f);
}

// ---------------------------------------------------------------
// depthwise conv [t][c]: Y = T * conv(X), written as bf16 hi/lo planes
// grid (T/256, H1/32, B), 256 thr
// ---------------------------------------------------------------
__global__ void k_conv() {
    int b = blockIdx.z, c0 = blockIdx.y * 32, t0 = blockIdx.x * 256;
    __shared__ float xs[264][32];
    int tid = threadIdx.x;
    int c = tid & 31, tr = tid >> 5;
    const float* X = g_X + (size_t)b * Tn * H1n + c0;
    for (int i = tr; i < 264; i += 8) {
        int t = t0 + i - 4;
        xs[i][c] = (t >= 0 && t < Tn) ? X[(size_t)t * H1n + c] : 0.f;
    }
    float w[KW];
    const float* wp = g_dwn + ((size_t)b * H1n + c0 + c) * KW;
#pragma unroll
    for (int k = 0; k < KW; k++) w[k] = wp[k];
    __syncthreads();
    size_t ybase = ((size_t)b * Tn + t0) * H1n + c0;
    for (int j = 0; j < 32; j++) {
        int t = tr * 32 + j;
        float s = 0.f;
#pragma unroll
        for (int k = 0; k < KW; k++) s += xs[t + k][c] * w[k];
        split_store(g_Yh, g_Yl, ybase + (size_t)t * H1n + c, s * (float)Tn);
    }
}

// ---------------------------------------------------------------
// bias2[b,d] = sum_c M[b,d,c]*d_b[b,c] + sum_o w2[d,o]*p_b[b,o] + w2b[d]
// ---------------------------------------------------------------
__global__ void k_bias2(const float* __restrict__ db, const float* __restrict__ w2w,
                        const float* __restrict__ pb, const float* __restrict__ w2b) {
    int d = blockIdx.x, b = blockIdx.y;
    int tid = threadIdx.x;
    size_t mrow = ((size_t)b * DIN + d) * H1n;
    const float* dbp = db + b * H1n;
    float acc = 0.f;
    for (int c = tid; c < H1n; c += 256) {
        float m = __bfloat162float(g_Mh[mrow + c]) + __bfloat162float(g_Ml[mrow + c]);
        acc += m * dbp[c];
    }
    const float* w2r = w2w + (size_t)d * H2n;
    const float* pbp = pb + b * H2n;
    for (int o = tid; o < H2n; o += 256) acc += w2r[o] * pbp[o];
    __shared__ float red[256];
    red[tid] = acc;
    __syncthreads();
    for (int s = 128; s > 0; s >>= 1) {
        if (tid < s) red[tid] += red[tid + s];
        __syncthreads();
    }
    if (tid == 0) g_bias2[b * DIN + d] = red[0] + w2b[d];
}

// ---------------------------------------------------------------
extern "C" void kernel_launch(void* const* d_in, const int* in_sizes, int n_in,
                              void* d_out, int out_size) {
    const float* inp = (const float*)d_in[0];   // [B,T,DIN]
    const float* dw  = (const float*)d_in[1];   // [B,H1,1,K]
    const float* dg  = (const float*)d_in[2];   // [B,H1]
    const float* db  = (const float*)d_in[3];   // [B,H1]
    const float* pw  = (const float*)d_in[4];   // [B,H1,H2,1]
    const float* pg  = (const float*)d_in[5];   // [B,H1]
    const float* pb  = (const float*)d_in[6];   // [B,H2]
    const float* w1w = (const float*)d_in[7];   // [H1,DIN]
    const float* w1b = (const float*)d_in[8];   // [H1]
    const float* w2w = (const float*)d_in[9];   // [DIN,H2]
    const float* w2b = (const float*)d_in[10];  // [DIN]
    float* out = (float*)d_out;                 // [B,T,DIN]
    (void)in_sizes; (void)n_in; (void)out_size;

    k_dwn<<<Bn, 256>>>(dw, dg);
    k_pinv<<<dim3(H2n / 256, Bn), 256>>>(pw);

    unsigned nb_inp = (unsigned)((size_t)Bn * Tn * DIN / 4 / 256);   // 6144
    unsigned nb_w1  = (unsigned)((size_t)H1n * DIN / 4 / 256);       // 384
    unsigned nb_w2  = (unsigned)((size_t)DIN * H2n / 4 / 256);       // 384
    unsigned nb_pw  = (unsigned)((size_t)Bn * H1n * H2n / 4 / 256);  // 16384
    k_cvt_inp<<<nb_inp, 256>>>(inp);
    k_cvt_w1<<<nb_w1, 256>>>(w1w);
    k_cvt_w2<<<nb_w2, 256>>>(w2w);
    k_cvt_pw<<<nb_pw, 256>>>(pw);

    k_mm1<<<dim3(H1n / 128, Tn / 128, Bn), 256>>>(w1b);
    k_conv<<<dim3(Tn / 256, H1n / 32, Bn), 256>>>();
    k_mmC<<<dim3(H1n / 128, DIN / 128, Bn), 256>>>(pg);
    k_bias2<<<dim3(DIN, Bn), 256>>>(db, w2w, pb, w2b);
    k_mmE<<<dim3(DIN / 128, Tn / 128, Bn), 256>>>(inp, out);
}

// round 9
// speedup vs baseline: 2.0648x; 1.0439x over previous
#include <cuda_runtime.h>
#include <cuda_bf16.h>
#include <math.h>
#include <stdint.h>

#define Bn   16
#define Tn   1024
#define DIN  384
#define H1n  1024
#define H2n  1024
#define KW   9

typedef __nv_bfloat16 bf16;

// -------- persistent scratch (device globals; referenced ONLY in device code) ----
__device__ float g_X[(size_t)Bn * Tn * H1n];        // mish(GEMM1): [b][t][c] fp32
__device__ bf16  g_Yh[(size_t)Bn * Tn * H1n];       // conv out hi: [b][t][c]
__device__ bf16  g_Yl[(size_t)Bn * Tn * H1n];       // conv out lo
__device__ bf16  g_ih[(size_t)Bn * Tn * DIN];       // input planes [b][t][k]
__device__ bf16  g_il[(size_t)Bn * Tn * DIN];
__device__ bf16  g_w1h[(size_t)H1n * DIN];          // w1 planes [c][k]
__device__ bf16  g_w1l[(size_t)H1n * DIN];
__device__ bf16  g_pwh[(size_t)Bn * H1n * H2n];     // pw*pinv planes [b][c][o]
__device__ bf16  g_pwl[(size_t)Bn * H1n * H2n];
__device__ bf16  g_w2h[(size_t)DIN * H2n];          // w2 planes [d][o]
__device__ bf16  g_w2l[(size_t)DIN * H2n];
__device__ bf16  g_Mh[(size_t)Bn * DIN * H1n];      // M planes [b][d][c]
__device__ bf16  g_Ml[(size_t)Bn * DIN * H1n];
__device__ float g_dwn[Bn * H1n * KW];
__device__ float g_pinv[Bn * H2n];
__device__ float g_bias2[Bn * DIN];

// ================= base-family PTX helpers =================
__device__ __forceinline__ uint32_t smem_to_u32(const void* p) {
    uint32_t a;
    asm("{ .reg .u64 t; cvta.to.shared.u64 t, %1; cvt.u32.u64 %0, t; }" : "=r"(a) : "l"(p));
    return a;
}
__device__ __forceinline__ void cp16(uint32_t dst, const void* src) {
    asm volatile("cp.async.cg.shared.global [%0], [%1], 16;" :: "r"(dst), "l"(src));
}
__device__ __forceinline__ void cp_commit() {
    asm volatile("cp.async.commit_group;" ::: "memory");
}
__device__ __forceinline__ void mma_bf16(float (&c)[4], const uint32_t (&a)[4],
                                         const uint32_t (&b)[2]) {
    asm volatile(
        "mma.sync.aligned.m16n8k16.row.col.f32.bf16.bf16.f32 "
        "{%0,%1,%2,%3}, {%4,%5,%6,%7}, {%8,%9}, {%0,%1,%2,%3};"
        : "+f"(c[0]), "+f"(c[1]), "+f"(c[2]), "+f"(c[3])
        : "r"(a[0]), "r"(a[1]), "r"(a[2]), "r"(a[3]), "r"(b[0]), "r"(b[1]));
}
__device__ __forceinline__ void ldsm4(uint32_t (&r)[4], uint32_t a) {
    asm volatile("ldmatrix.sync.aligned.m8n8.x4.shared.b16 {%0,%1,%2,%3}, [%4];"
                 : "=r"(r[0]), "=r"(r[1]), "=r"(r[2]), "=r"(r[3]) : "r"(a));
}
__device__ __forceinline__ void ldsm2(uint32_t (&r)[2], uint32_t a) {
    asm volatile("ldmatrix.sync.aligned.m8n8.x2.shared.b16 {%0,%1}, [%2];"
                 : "=r"(r[0]), "=r"(r[1]) : "r"(a));
}

// ================= GEMM tile geometry =================
// CTA tile 128x128, K-tile 16 bf16, 2-stage cp.async pipeline, STATIC smem.
// Rows padded to 48B (12 words): ldmatrix row addrs (12r words) mod 32 banks
// cover disjoint 4-bank groups -> conflict-free.
#define PLANE_B 6144u            // 128 rows * 48 B
#define STAGE_B (4u * PLANE_B)   // Ah, Al, Bh, Bl = 24576
#define GSMEM   (2u * STAGE_B)   // 49152 = static smem limit, no opt-in needed

__device__ __forceinline__ void load_stage(uint32_t sb, int buf,
        const bf16* __restrict__ Ah, const bf16* __restrict__ Al, int lda,
        const bf16* __restrict__ Bh, const bf16* __restrict__ Bl, int ldb,
        int k0, int tid) {
    uint32_t base = sb + (uint32_t)buf * STAGE_B;
    int r = tid >> 1, q = tid & 1;          // row 0..127, 16B chunk 0..1
    uint32_t d = base + r * 48 + q * 16;
    size_t ga = (size_t)r * lda + k0 + q * 8;
    size_t gb = (size_t)r * ldb + k0 + q * 8;
    cp16(d,               Ah + ga);
    cp16(d + PLANE_B,     Al + ga);
    cp16(d + 2 * PLANE_B, Bh + gb);
    cp16(d + 3 * PLANE_B, Bl + gb);
}

__device__ __forceinline__ void compute_stage(uint32_t sb, int buf,
                                              int wm, int wn, int lane,
                                              float acc[4][4][4]) {
    uint32_t base = sb + (uint32_t)buf * STAGE_B;
    int r = lane & 7, grp = lane >> 3;
    uint32_t a_off = (uint32_t)((r + ((grp & 1) << 3)) * 48 + ((grp >> 1) << 4));
    uint32_t b_off = (uint32_t)(r * 48 + ((grp & 1) << 4));
    uint32_t ah[4][4], al[4][4], bh[4][2], bl[4][2];
#pragma unroll
    for (int mt = 0; mt < 4; mt++) {
        uint32_t rowb = (uint32_t)(wm * 64 + mt * 16) * 48;
        ldsm4(ah[mt], base + rowb + a_off);
        ldsm4(al[mt], base + PLANE_B + rowb + a_off);
    }
#pragma unroll
    for (int nt = 0; nt < 4; nt++) {
        uint32_t rowb = (uint32_t)(wn * 32 + nt * 8) * 48;
        ldsm2(bh[nt], base + 2 * PLANE_B + rowb + b_off);
        ldsm2(bl[nt], base + 3 * PLANE_B + rowb + b_off);
    }
#pragma unroll
    for (int mt = 0; mt < 4; mt++)
#pragma unroll
        for (int nt = 0; nt < 4; nt++) {
            mma_bf16(acc[mt][nt], ah[mt], bh[nt]);
            mma_bf16(acc[mt][nt], ah[mt], bl[nt]);
            mma_bf16(acc[mt][nt], al[mt], bh[nt]);
        }
}

// Single barrier per iteration: next-stage cp.async issued AFTER the sync,
// so the one sync also protects the buffer being overwritten.
__device__ __forceinline__ void gemm_main(uint32_t sb,
        const bf16* Ah, const bf16* Al, int lda,
        const bf16* Bh, const bf16* Bl, int ldb,
        int kiters, float acc[4][4][4], int tid) {
    int wid = tid >> 5, lane = tid & 31, wm = wid & 1, wn = wid >> 1;
#pragma unroll
    for (int i = 0; i < 4; i++)
#pragma unroll
        for (int j = 0; j < 4; j++)
#pragma unroll
            for (int k = 0; k < 4; k++) acc[i][j][k] = 0.f;

    load_stage(sb, 0, Ah, Al, lda, Bh, Bl, ldb, 0, tid);
    cp_commit();
    for (int it = 0; it < kiters; it++) {
        asm volatile("cp.async.wait_group 0;" ::: "memory");
        __syncthreads();
        if (it + 1 < kiters) {
            load_stage(sb, (it + 1) & 1, Ah, Al, lda, Bh, Bl, ldb, (it + 1) * 16, tid);
            cp_commit();
        }
        compute_stage(sb, it & 1, wm, wn, lane, acc);
    }
    __syncthreads();   // smem about to be reused as epilogue stage
}

// mish(x) = x*tanh(softplus(x)) = x*(u^2+2u)/(u^2+2u+2), u=e^x  (exact algebra)
__device__ __forceinline__ float mishf(float x) {
    if (x > 15.f) return x;
    float u = expf(x);
    float t = u * (u + 2.f);
    return x * __fdividef(t, t + 2.f);
}
__device__ __forceinline__ void split_store(bf16* hi, bf16* lo, size_t i, float v) {
    bf16 h = __float2bfloat16(v);
    hi[i] = h;
    lo[i] = __float2bfloat16(v - __bfloat162float(h));
}
__device__ __forceinline__ uint32_t pack_bf2(float a, float b) {
    __nv_bfloat162 v = __floats2bfloat162_rn(a, b);
    return *reinterpret_cast<uint32_t*>(&v);
}

// ---------------------------------------------------------------
// GEMM1: D[c,t] = sum_k w1[c,k]*in[b,t,k]; X[b][t][c] = mish(D + w1b[c])
// grid (H1/128, T/128, B), 256 thr
// ---------------------------------------------------------------
__global__ void __launch_bounds__(256)
k_mm1(const float* __restrict__ w1b) {
    __shared__ __align__(16) char smem[GSMEM];
    uint32_t sb = smem_to_u32(smem);
    int tid = threadIdx.x;
    int b = blockIdx.z, c0 = blockIdx.x * 128, t0 = blockIdx.y * 128;
    float acc[4][4][4];
    gemm_main(sb,
              g_w1h + (size_t)c0 * DIN, g_w1l + (size_t)c0 * DIN, DIN,
              g_ih + ((size_t)b * Tn + t0) * DIN, g_il + ((size_t)b * Tn + t0) * DIN, DIN,
              DIN / 16, acc, tid);
    int wid = tid >> 5, lane = tid & 31, wm = wid & 1, wn = wid >> 1;
    int g = lane >> 2, tig = lane & 3;
    float* stage = (float*)smem;                        // [64][132]
    for (int h = 0; h < 2; h++) {
        if ((wn >> 1) == h) {
            int tl0 = (wn & 1) * 32;
#pragma unroll
            for (int mt = 0; mt < 4; mt++) {
                int c = wm * 64 + mt * 16 + g;
                float b0 = w1b[c0 + c], b1 = w1b[c0 + c + 8];
#pragma unroll
                for (int nt = 0; nt < 4; nt++) {
                    int t = tl0 + nt * 8 + tig * 2;
                    stage[t * 132 + c]           = mishf(acc[mt][nt][0] + b0);
                    stage[(t + 1) * 132 + c]     = mishf(acc[mt][nt][1] + b0);
                    stage[t * 132 + c + 8]       = mishf(acc[mt][nt][2] + b1);
                    stage[(t + 1) * 132 + c + 8] = mishf(acc[mt][nt][3] + b1);
                }
            }
        }
        __syncthreads();
#pragma unroll
        for (int j = 0; j < 8; j++) {
            int idx = tid + j * 256;
            int t = idx >> 5, c4 = (idx & 31) * 4;
            float4 v = *(const float4*)&stage[t * 132 + c4];
            *(float4*)&g_X[((size_t)b * Tn + t0 + h * 64 + t) * H1n + c0 + c4] = v;
        }
        __syncthreads();
    }
}

// ---------------------------------------------------------------
// GEMMC: D[c,d] = sum_o pwn[b,c,o]*w2[d,o]; M[b][d][c] = D*pg[b,c] (hi/lo planes)
// grid (H1/128, DIN/128, B); M-dim = c, N-dim = d
// ---------------------------------------------------------------
__global__ void __launch_bounds__(256)
k_mmC(const float* __restrict__ pg) {
    __shared__ __align__(16) char smem[GSMEM];
    uint32_t sb = smem_to_u32(smem);
    int tid = threadIdx.x;
    int b = blockIdx.z, c0 = blockIdx.x * 128, d0 = blockIdx.y * 128;
    float acc[4][4][4];
    gemm_main(sb,
              g_pwh + ((size_t)b * H1n + c0) * H2n, g_pwl + ((size_t)b * H1n + c0) * H2n, H2n,
              g_w2h + (size_t)d0 * H2n, g_w2l + (size_t)d0 * H2n, H2n,
              H2n / 16, acc, tid);
    int wid = tid >> 5, lane = tid & 31, wm = wid & 1, wn = wid >> 1;
    int g = lane >> 2, tig = lane & 3;
    float* stage = (float*)smem;                        // [64][132] (rows = d)
    for (int h = 0; h < 2; h++) {
        if ((wn >> 1) == h) {
            int dl0 = (wn & 1) * 32;
#pragma unroll
            for (int mt = 0; mt < 4; mt++) {
                int c = wm * 64 + mt * 16 + g;
                float p0 = pg[b * H1n + c0 + c], p1 = pg[b * H1n + c0 + c + 8];
#pragma unroll
                for (int nt = 0; nt < 4; nt++) {
                    int d = dl0 + nt * 8 + tig * 2;
                    stage[d * 132 + c]           = acc[mt][nt][0] * p0;
                    stage[(d + 1) * 132 + c]     = acc[mt][nt][1] * p0;
                    stage[d * 132 + c + 8]       = acc[mt][nt][2] * p1;
                    stage[(d + 1) * 132 + c + 8] = acc[mt][nt][3] * p1;
                }
            }
        }
        __syncthreads();
#pragma unroll
        for (int j = 0; j < 8; j++) {
            int idx = tid + j * 256;
            int d = idx >> 5, c4 = (idx & 31) * 4;
            float4 v = *(const float4*)&stage[d * 132 + c4];
            size_t row = ((size_t)b * DIN + d0 + h * 64 + d) * H1n + c0 + c4;
            bf16 hx = __float2bfloat16(v.x), hy = __float2bfloat16(v.y);
            bf16 hz = __float2bfloat16(v.z), hw = __float2bfloat16(v.w);
            uint32_t hp0, hp1;
            { __nv_bfloat162 t2 = {hx, hy}; hp0 = *reinterpret_cast<uint32_t*>(&t2); }
            { __nv_bfloat162 t2 = {hz, hw}; hp1 = *reinterpret_cast<uint32_t*>(&t2); }
            *(uint2*)&g_Mh[row] = make_uint2(hp0, hp1);
            uint32_t lp0 = pack_bf2(v.x - __bfloat162float(hx), v.y - __bfloat162float(hy));
            uint32_t lp1 = pack_bf2(v.z - __bfloat162float(hz), v.w - __bfloat162float(hw));
            *(uint2*)&g_Ml[row] = make_uint2(lp0, lp1);
        }
        __syncthreads();
    }
}

// ---------------------------------------------------------------
// GEMME: D[d,t] = sum_c M[b,d,c]*Y[b,t,c]; out = D + bias2 + residual
// grid (DIN/128, T/128, B); M-dim = d, N-dim = t
// ---------------------------------------------------------------
__global__ void __launch_bounds__(256)
k_mmE(const float* __restrict__ inp, float* __restrict__ out) {
    __shared__ __align__(16) char smem[GSMEM];
    uint32_t sb = smem_to_u32(smem);
    int tid = threadIdx.x;
    int b = blockIdx.z, d0 = blockIdx.x * 128, t0 = blockIdx.y * 128;
    float acc[4][4][4];
    gemm_main(sb,
              g_Mh + ((size_t)b * DIN + d0) * H1n, g_Ml + ((size_t)b * DIN + d0) * H1n, H1n,
              g_Yh + ((size_t)b * Tn + t0) * H1n, g_Yl + ((size_t)b * Tn + t0) * H1n, H1n,
              H1n / 16, acc, tid);
    int wid = tid >> 5, lane = tid & 31, wm = wid & 1, wn = wid >> 1;
    int g = lane >> 2, tig = lane & 3;
    float* stage = (float*)smem;                        // [64][132] (rows = t)
    for (int h = 0; h < 2; h++) {
        if ((wn >> 1) == h) {
            int tl0 = (wn & 1) * 32;
#pragma unroll
            for (int mt = 0; mt < 4; mt++) {
                int d = wm * 64 + mt * 16 + g;
                float b0 = g_bias2[b * DIN + d0 + d], b1 = g_bias2[b * DIN + d0 + d + 8];
#pragma unroll
                for (int nt = 0; nt < 4; nt++) {
                    int t = tl0 + nt * 8 + tig * 2;
                    stage[t * 132 + d]           = acc[mt][nt][0] + b0;
                    stage[(t + 1) * 132 + d]     = acc[mt][nt][1] + b0;
                    stage[t * 132 + d + 8]       = acc[mt][nt][2] + b1;
                    stage[(t + 1) * 132 + d + 8] = acc[mt][nt][3] + b1;
                }
            }
        }
        __syncthreads();
#pragma unroll
        for (int j = 0; j < 8; j++) {
            int idx = tid + j * 256;
            int t = idx >> 5, c4 = (idx & 31) * 4;
            float4 v = *(const float4*)&stage[t * 132 + c4];
            size_t a = ((size_t)b * Tn + t0 + h * 64 + t) * DIN + d0 + c4;
            float4 r = *(const float4*)&inp[a];
            v.x += r.x; v.y += r.y; v.z += r.z; v.w += r.w;
            *(float4*)&out[a] = v;
        }
        __syncthreads();
    }
}

// ---------------------------------------------------------------
// dedicated convert kernels — device globals referenced ONLY in device code
// ---------------------------------------------------------------
__global__ void k_cvt_inp(const float* __restrict__ s) {
    size_t i = (size_t)blockIdx.x * 256 + threadIdx.x;
    float4 v = ((const float4*)s)[i];
    size_t o = i * 4;
    split_store(g_ih, g_il, o + 0, v.x);
    split_store(g_ih, g_il, o + 1, v.y);
    split_store(g_ih, g_il, o + 2, v.z);
    split_store(g_ih, g_il, o + 3, v.w);
}
__global__ void k_cvt_w1(const float* __restrict__ s) {
    size_t i = (size_t)blockIdx.x * 256 + threadIdx.x;
    float4 v = ((const float4*)s)[i];
    size_t o = i * 4;
    split_store(g_w1h, g_w1l, o + 0, v.x);
    split_store(g_w1h, g_w1l, o + 1, v.y);
    split_store(g_w1h, g_w1l, o + 2, v.z);
    split_store(g_w1h, g_w1l, o + 3, v.w);
}
__global__ void k_cvt_w2(const float* __restrict__ s) {
    size_t i = (size_t)blockIdx.x * 256 + threadIdx.x;
    float4 v = ((const float4*)s)[i];
    size_t o = i * 4;
    split_store(g_w2h, g_w2l, o + 0, v.x);
    split_store(g_w2h, g_w2l, o + 1, v.y);
    split_store(g_w2h, g_w2l, o + 2, v.z);
    split_store(g_w2h, g_w2l, o + 3, v.w);
}

// pw * pinv[b,o] -> hi/lo planes
__global__ void k_cvt_pw(const float* __restrict__ pw) {
    size_t i = (size_t)blockIdx.x * 256 + threadIdx.x;   // n4 = 4M exactly
    size_t idx = i * 4;
    int o = (int)(idx & (H2n - 1));
    int b = (int)(idx >> 20);
    float4 v = ((const float4*)pw)[i];
    float4 sc = *(const float4*)(g_pinv + b * H2n + o);
    split_store(g_pwh, g_pwl, idx + 0, v.x * sc.x);
    split_store(g_pwh, g_pwl, idx + 1, v.y * sc.y);
    split_store(g_pwh, g_pwl, idx + 2, v.z * sc.z);
    split_store(g_pwh, g_pwl, idx + 3, v.w * sc.w);
}

// ---------------------------------------------------------------
// normalized depthwise weights
// ---------------------------------------------------------------
__global__ void k_dwn(const float* __restrict__ dw, const float* __restrict__ dg) {
    int b = blockIdx.x;
    __shared__ float red[256];
    __shared__ float nrm[KW];
    int tid = threadIdx.x;
    float acc[KW];
#pragma unroll
    for (int k = 0; k < KW; k++) acc[k] = 0.f;
    for (int c = tid; c < H1n; c += 256) {
        const float* p = dw + ((size_t)b * H1n + c) * KW;
#pragma unroll
        for (int k = 0; k < KW; k++) { float v = p[k]; acc[k] += v * v; }
    }
    for (int k = 0; k < KW; k++) {
        red[tid] = acc[k];
        __syncthreads();
        for (int s = 128; s > 0; s >>= 1) {
            if (tid < s) red[tid] += red[tid + s];
            __syncthreads();
        }
        if (tid == 0) nrm[k] = fmaxf(sqrtf(red[0]), 1e-12f);
        __syncthreads();
    }
    for (int c = tid; c < H1n; c += 256) {
        float g = dg[b * H1n + c];
        const float* p = dw + ((size_t)b * H1n + c) * KW;
        float* q = g_dwn + ((size_t)b * H1n + c) * KW;
#pragma unroll
        for (int k = 0; k < KW; k++) q[k] = p[k] / nrm[k] * g;
    }
}

// ---------------------------------------------------------------
// g_pinv[b,o] = 1/||p_w[b,:,o]||
// ---------------------------------------------------------------
__global__ void k_pinv(const float* __restrict__ pw) {
    int b = blockIdx.y;
    int o = blockIdx.x * 256 + threadIdx.x;
    const float* base = pw + (size_t)b * H1n * H2n + o;
    float acc = 0.f;
#pragma unroll 8
    for (int c = 0; c < H1n; c++) {
        float v = base[(size_t)c * H2n];
        acc += v * v;
    }
    g_pinv[b * H2n + o] = 1.0f / fmaxf(sqrtf(acc), 1e-12f);
}

// ---------------------------------------------------------------
// depthwise conv [t][c]: Y = T * conv(X), written as bf16 hi/lo planes
// grid (T/256, H1/32, B), 256 thr
// ---------------------------------------------------------------
__global__ void k_conv() {
    int b = blockIdx.z, c0 = blockIdx.y * 32, t0 = blockIdx.x * 256;
    __shared__ float xs[264][32];
    int tid = threadIdx.x;
    int c = tid & 31, tr = tid >> 5;
    const float* X = g_X + (size_t)b * Tn * H1n + c0;
    for (int i = tr; i < 264; i += 8) {
        int t = t0 + i - 4;
        xs[i][c] = (t >= 0 && t < Tn) ? X[(size_t)t * H1n + c] : 0.f;
    }
    float w[KW];
    const float* wp = g_dwn + ((size_t)b * H1n + c0 + c) * KW;
#pragma unroll
    for (int k = 0; k < KW; k++) w[k] = wp[k];
    __syncthreads();
    size_t ybase = ((size_t)b * Tn + t0) * H1n + c0;
    for (int j = 0; j < 32; j++) {
        int t = tr * 32 + j;
        float s = 0.f;
#pragma unroll
        for (int k = 0; k < KW; k++) s += xs[t + k][c] * w[k];
        split_store(g_Yh, g_Yl, ybase + (size_t)t * H1n + c, s * (float)Tn);
    }
}

// ---------------------------------------------------------------
// bias2[b,d] = sum_c M[b,d,c]*d_b[b,c] + sum_o w2[d,o]*p_b[b,o] + w2b[d]
// ---------------------------------------------------------------
__global__ void k_bias2(const float* __restrict__ db, const float* __restrict__ w2w,
                        const float* __restrict__ pb, const float* __restrict__ w2b) {
    int d = blockIdx.x, b = blockIdx.y;
    int tid = threadIdx.x;
    size_t mrow = ((size_t)b * DIN + d) * H1n;
    const float* dbp = db + b * H1n;
    float acc = 0.f;
    for (int c = tid; c < H1n; c += 256) {
        float m = __bfloat162float(g_Mh[mrow + c]) + __bfloat162float(g_Ml[mrow + c]);
        acc += m * dbp[c];
    }
    const float* w2r = w2w + (size_t)d * H2n;
    const float* pbp = pb + b * H2n;
    for (int o = tid; o < H2n; o += 256) acc += w2r[o] * pbp[o];
    __shared__ float red[256];
    red[tid] = acc;
    __syncthreads();
    for (int s = 128; s > 0; s >>= 1) {
        if (tid < s) red[tid] += red[tid + s];
        __syncthreads();
    }
    if (tid == 0) g_bias2[b * DIN + d] = red[0] + w2b[d];
}

// ---------------------------------------------------------------
extern "C" void kernel_launch(void* const* d_in, const int* in_sizes, int n_in,
                              void* d_out, int out_size) {
    const float* inp = (const float*)d_in[0];   // [B,T,DIN]
    const float* dw  = (const float*)d_in[1];   // [B,H1,1,K]
    const float* dg  = (const float*)d_in[2];   // [B,H1]
    const float* db  = (const float*)d_in[3];   // [B,H1]
    const float* pw  = (const float*)d_in[4];   // [B,H1,H2,1]
    const float* pg  = (const float*)d_in[5];   // [B,H1]
    const float* pb  = (const float*)d_in[6];   // [B,H2]
    const float* w1w = (const float*)d_in[7];   // [H1,DIN]
    const float* w1b = (const float*)d_in[8];   // [H1]
    const float* w2w = (const float*)d_in[9];   // [DIN,H2]
    const float* w2b = (const float*)d_in[10];  // [DIN]
    float* out = (float*)d_out;                 // [B,T,DIN]
    (void)in_sizes; (void)n_in; (void)out_size;

    k_dwn<<<Bn, 256>>>(dw, dg);
    k_pinv<<<dim3(H2n / 256, Bn), 256>>>(pw);

    unsigned nb_inp = (unsigned)((size_t)Bn * Tn * DIN / 4 / 256);   // 6144
    unsigned nb_w1  = (unsigned)((size_t)H1n * DIN / 4 / 256);       // 384
    unsigned nb_w2  = (unsigned)((size_t)DIN * H2n / 4 / 256);       // 384
    unsigned nb_pw  = (unsigned)((size_t)Bn * H1n * H2n / 4 / 256);  // 16384
    k_cvt_inp<<<nb_inp, 256>>>(inp);
    k_cvt_w1<<<nb_w1, 256>>>(w1w);
    k_cvt_w2<<<nb_w2, 256>>>(w2w);
    k_cvt_pw<<<nb_pw, 256>>>(pw);

    k_mm1<<<dim3(H1n / 128, Tn / 128, Bn), 256>>>(w1b);
    k_conv<<<dim3(Tn / 256, H1n / 32, Bn), 256>>>();
    k_mmC<<<dim3(H1n / 128, DIN / 128, Bn), 256>>>(pg);
    k_bias2<<<dim3(DIN, Bn), 256>>>(db, w2w, pb, w2b);
    k_mmE<<<dim3(DIN / 128, Tn / 128, Bn), 256>>>(inp, out);
}

// round 11
// speedup vs baseline: 2.4061x; 1.1653x over previous
#include <cuda_runtime.h>
#include <cuda_bf16.h>
#include <math.h>
#include <stdint.h>

#define Bn   16
#define Tn   1024
#define DIN  384
#define H1n  1024
#define H2n  1024
#define KW   9

// -------- persistent scratch (device globals; referenced ONLY in device code) ----
__device__ float g_X[(size_t)Bn * Tn * H1n];      // mish(GEMM1): [b][t][c]
__device__ float g_Y[(size_t)Bn * Tn * H1n];      // conv out (tf32-rounded): [b][t][c]
__device__ float g_ir[(size_t)Bn * Tn * DIN];     // rna(input) [b][t][k]
__device__ float g_w1r[(size_t)H1n * DIN];        // rna(w1)    [c][k]
__device__ float g_pwr[(size_t)Bn * H1n * H2n];   // rna(pw)    [b][c][o]
__device__ float g_w2s[(size_t)Bn * DIN * H2n];   // rna(w2*pinv) [b][d][o]
__device__ float g_M[(size_t)Bn * DIN * H1n];     // M (tf32-rounded) [b][d][c]
__device__ float g_dwn[Bn * H1n * KW];
__device__ float g_pinv[Bn * H2n];
__device__ float g_bias2[Bn * DIN];

// ================= base-family PTX helpers =================
__device__ __forceinline__ uint32_t smem_to_u32(const void* p) {
    uint32_t a;
    asm("{ .reg .u64 t; cvta.to.shared.u64 t, %1; cvt.u32.u64 %0, t; }" : "=r"(a) : "l"(p));
    return a;
}
__device__ __forceinline__ void cp16(uint32_t dst, const void* src) {
    asm volatile("cp.async.cg.shared.global [%0], [%1], 16;" :: "r"(dst), "l"(src));
}
__device__ __forceinline__ void cp_commit() {
    asm volatile("cp.async.commit_group;" ::: "memory");
}
__device__ __forceinline__ void mma_tf32(float (&c)[4], const uint32_t (&a)[4],
                                         const uint32_t (&b)[2]) {
    asm volatile(
        "mma.sync.aligned.m16n8k8.row.col.f32.tf32.tf32.f32 "
        "{%0,%1,%2,%3}, {%4,%5,%6,%7}, {%8,%9}, {%0,%1,%2,%3};"
        : "+f"(c[0]), "+f"(c[1]), "+f"(c[2]), "+f"(c[3])
        : "r"(a[0]), "r"(a[1]), "r"(a[2]), "r"(a[3]), "r"(b[0]), "r"(b[1]));
}
// round-to-nearest tf32 (unbiased), returned as fp32 bit pattern
__device__ __forceinline__ float rna(float f) {
    uint32_t r;
    asm("cvt.rna.tf32.f32 %0, %1;" : "=r"(r) : "f"(f));
    return __uint_as_float(r);
}

// ================= GEMM tile geometry =================
// CTA tile 128x128, K-tile 16 fp32(tf32), 2-stage cp.async pipeline, STATIC smem.
// Rows padded to 80B (20 words): fragment LDS banks (20r + tig) mod 32 all distinct.
#define PROW_W   20u
#define PLANE_B  10240u          // 128 rows * 80 B
#define PLANE_W  2560u
#define STAGE_B  (2u * PLANE_B)  // A, B = 20480
#define STAGE_W  (2u * PLANE_W)
#define GSMEM    (2u * STAGE_B)  // 40960 <= 48K static limit

__device__ __forceinline__ void load_stage(uint32_t sb, int buf,
        const float* __restrict__ A, int lda,
        const float* __restrict__ B, int ldb,
        int k0, int tid) {
    uint32_t base = sb + (uint32_t)buf * STAGE_B;
#pragma unroll
    for (int j = 0; j < 4; j++) {
        int cid = tid + j * 256;            // 0..1023
        int plane = cid >> 9;               // 0:A 1:B
        int idx = cid & 511;
        int r = idx >> 2, q = idx & 3;      // row 0..127, 16B chunk 0..3
        uint32_t d = base + (uint32_t)plane * PLANE_B + r * 80 + q * 16;
        const float* s = (plane ? B + (size_t)r * ldb : A + (size_t)r * lda) + k0 + q * 4;
        cp16(d, s);
    }
}

__device__ __forceinline__ void compute_stage(const uint32_t* __restrict__ W, int buf,
                                              int wm, int wn, int lane,
                                              float acc[4][4][4]) {
    uint32_t Ab = (uint32_t)buf * STAGE_W;
    uint32_t Bb = Ab + PLANE_W;
    int g = lane >> 2, tig = lane & 3;
#pragma unroll
    for (int ks = 0; ks < 2; ks++) {
        int ko = ks * 8 + tig;
        uint32_t a[4][4], bf[4][2];
#pragma unroll
        for (int mt = 0; mt < 4; mt++) {
            uint32_t r0 = Ab + (uint32_t)(wm * 64 + mt * 16 + g) * PROW_W + ko;
            a[mt][0] = W[r0];       a[mt][1] = W[r0 + 8 * PROW_W];
            a[mt][2] = W[r0 + 4];   a[mt][3] = W[r0 + 8 * PROW_W + 4];
        }
#pragma unroll
        for (int nt = 0; nt < 4; nt++) {
            uint32_t r0 = Bb + (uint32_t)(wn * 32 + nt * 8 + g) * PROW_W + ko;
            bf[nt][0] = W[r0];  bf[nt][1] = W[r0 + 4];
        }
#pragma unroll
        for (int mt = 0; mt < 4; mt++)
#pragma unroll
            for (int nt = 0; nt < 4; nt++)
                mma_tf32(acc[mt][nt], a[mt], bf[nt]);
    }
}

// Single barrier per iteration; next-stage cp.async issued AFTER the sync.
__device__ __forceinline__ void gemm_main(const uint32_t* W, uint32_t sb,
        const float* A, int lda, const float* B, int ldb,
        int kiters, float acc[4][4][4], int tid) {
    int wid = tid >> 5, lane = tid & 31, wm = wid & 1, wn = wid >> 1;
#pragma unroll
    for (int i = 0; i < 4; i++)
#pragma unroll
        for (int j = 0; j < 4; j++)
#pragma unroll
            for (int k = 0; k < 4; k++) acc[i][j][k] = 0.f;

    load_stage(sb, 0, A, lda, B, ldb, 0, tid);
    cp_commit();
    for (int it = 0; it < kiters; it++) {
        asm volatile("cp.async.wait_group 0;" ::: "memory");
        __syncthreads();
        if (it + 1 < kiters) {
            load_stage(sb, (it + 1) & 1, A, lda, B, ldb, (it + 1) * 16, tid);
            cp_commit();
        }
        compute_stage(W, it & 1, wm, wn, lane, acc);
    }
    __syncthreads();   // smem about to be reused as epilogue stage
}

// mish(x) = x*(u^2+2u)/(u^2+2u+2), u=e^x
__device__ __forceinline__ float mishf(float x) {
    if (x > 15.f) return x;
    float u = expf(x);
    float t = u * (u + 2.f);
    return x * __fdividef(t, t + 2.f);
}

// ---------------------------------------------------------------
// GEMM1: D[c,t] = sum_k w1r[c,k]*ir[b,t,k]; X[b][t][c] = mish(D + w1b[c])
// grid (H1/128, T/128, B), 256 thr
// ---------------------------------------------------------------
__global__ void __launch_bounds__(256, 2)
k_mm1(const float* __restrict__ w1b) {
    __shared__ __align__(16) char smem[GSMEM];
    uint32_t sb = smem_to_u32(smem);
    const uint32_t* W = (const uint32_t*)smem;
    int tid = threadIdx.x;
    int b = blockIdx.z, c0 = blockIdx.x * 128, t0 = blockIdx.y * 128;
    float acc[4][4][4];
    gemm_main(W, sb,
              g_w1r + (size_t)c0 * DIN, DIN,
              g_ir + ((size_t)b * Tn + t0) * DIN, DIN,
              DIN / 16, acc, tid);
    int wid = tid >> 5, lane = tid & 31, wm = wid & 1, wn = wid >> 1;
    int g = lane >> 2, tig = lane & 3;
    float* stage = (float*)smem;                        // [64][132]
    for (int h = 0; h < 2; h++) {
        if ((wn >> 1) == h) {
            int tl0 = (wn & 1) * 32;
#pragma unroll
            for (int mt = 0; mt < 4; mt++) {
                int c = wm * 64 + mt * 16 + g;
                float b0 = w1b[c0 + c], b1 = w1b[c0 + c + 8];
#pragma unroll
                for (int nt = 0; nt < 4; nt++) {
                    int t = tl0 + nt * 8 + tig * 2;
                    stage[t * 132 + c]           = mishf(acc[mt][nt][0] + b0);
                    stage[(t + 1) * 132 + c]     = mishf(acc[mt][nt][1] + b0);
                    stage[t * 132 + c + 8]       = mishf(acc[mt][nt][2] + b1);
                    stage[(t + 1) * 132 + c + 8] = mishf(acc[mt][nt][3] + b1);
                }
            }
        }
        __syncthreads();
#pragma unroll
        for (int j = 0; j < 8; j++) {
            int idx = tid + j * 256;
            int t = idx >> 5, c4 = (idx & 31) * 4;
            float4 v = *(const float4*)&stage[t * 132 + c4];
            *(float4*)&g_X[((size_t)b * Tn + t0 + h * 64 + t) * H1n + c0 + c4] = v;
        }
        __syncthreads();
    }
}

// ---------------------------------------------------------------
// GEMMC: D[c,d] = sum_o pwr[b,c,o]*w2s[b,d,o]; M[b][d][c] = rna(D*pg[b,c])
// grid (H1/128, DIN/128, B); M-dim = c, N-dim = d
// ---------------------------------------------------------------
__global__ void __launch_bounds__(256, 2)
k_mmC(const float* __restrict__ pg) {
    __shared__ __align__(16) char smem[GSMEM];
    uint32_t sb = smem_to_u32(smem);
    const uint32_t* W = (const uint32_t*)smem;
    int tid = threadIdx.x;
    int b = blockIdx.z, c0 = blockIdx.x * 128, d0 = blockIdx.y * 128;
    float acc[4][4][4];
    gemm_main(W, sb,
              g_pwr + ((size_t)b * H1n + c0) * H2n, H2n,
              g_w2s + ((size_t)b * DIN + d0) * H2n, H2n,
              H2n / 16, acc, tid);
    int wid = tid >> 5, lane = tid & 31, wm = wid & 1, wn = wid >> 1;
    int g = lane >> 2, tig = lane & 3;
    float* stage = (float*)smem;                        // [64][132] (rows = d)
    for (int h = 0; h < 2; h++) {
        if ((wn >> 1) == h) {
            int dl0 = (wn & 1) * 32;
#pragma unroll
            for (int mt = 0; mt < 4; mt++) {
                int c = wm * 64 + mt * 16 + g;
                float p0 = pg[b * H1n + c0 + c], p1 = pg[b * H1n + c0 + c + 8];
#pragma unroll
                for (int nt = 0; nt < 4; nt++) {
                    int d = dl0 + nt * 8 + tig * 2;
                    stage[d * 132 + c]           = acc[mt][nt][0] * p0;
                    stage[(d + 1) * 132 + c]     = acc[mt][nt][1] * p0;
                    stage[d * 132 + c + 8]       = acc[mt][nt][2] * p1;
                    stage[(d + 1) * 132 + c + 8] = acc[mt][nt][3] * p1;
                }
            }
        }
        __syncthreads();
#pragma unroll
        for (int j = 0; j < 8; j++) {
            int idx = tid + j * 256;
            int d = idx >> 5, c4 = (idx & 31) * 4;
            float4 v = *(const float4*)&stage[d * 132 + c4];
            v.x = rna(v.x); v.y = rna(v.y); v.z = rna(v.z); v.w = rna(v.w);
            *(float4*)&g_M[((size_t)b * DIN + d0 + h * 64 + d) * H1n + c0 + c4] = v;
        }
        __syncthreads();
    }
}

// ---------------------------------------------------------------
// GEMME: D[d,t] = sum_c M[b,d,c]*Y[b,t,c]; out = D + bias2 + residual
// grid (DIN/128, T/128, B); M-dim = d, N-dim = t
// ---------------------------------------------------------------
__global__ void __launch_bounds__(256, 2)
k_mmE(const float* __restrict__ inp, float* __restrict__ out) {
    __shared__ __align__(16) char smem[GSMEM];
    uint32_t sb = smem_to_u32(smem);
    const uint32_t* W = (const uint32_t*)smem;
    int tid = threadIdx.x;
    int b = blockIdx.z, d0 = blockIdx.x * 128, t0 = blockIdx.y * 128;
    float acc[4][4][4];
    gemm_main(W, sb,
              g_M + ((size_t)b * DIN + d0) * H1n, H1n,
              g_Y + ((size_t)b * Tn + t0) * H1n, H1n,
              H1n / 16, acc, tid);
    int wid = tid >> 5, lane = tid & 31, wm = wid & 1, wn = wid >> 1;
    int g = lane >> 2, tig = lane & 3;
    float* stage = (float*)smem;                        // [64][132] (rows = t)
    for (int h = 0; h < 2; h++) {
        if ((wn >> 1) == h) {
            int tl0 = (wn & 1) * 32;
#pragma unroll
            for (int mt = 0; mt < 4; mt++) {
                int d = wm * 64 + mt * 16 + g;
                float b0 = g_bias2[b * DIN + d0 + d], b1 = g_bias2[b * DIN + d0 + d + 8];
#pragma unroll
                for (int nt = 0; nt < 4; nt++) {
                    int t = tl0 + nt * 8 + tig * 2;
                    stage[t * 132 + d]           = acc[mt][nt][0] + b0;
                    stage[(t + 1) * 132 + d]     = acc[mt][nt][1] + b0;
                    stage[t * 132 + d + 8]       = acc[mt][nt][2] + b1;
                    stage[(t + 1) * 132 + d + 8] = acc[mt][nt][3] + b1;
                }
            }
        }
        __syncthreads();
#pragma unroll
        for (int j = 0; j < 8; j++) {
            int idx = tid + j * 256;
            int t = idx >> 5, c4 = (idx & 31) * 4;
            float4 v = *(const float4*)&stage[t * 132 + c4];
            size_t a = ((size_t)b * Tn + t0 + h * 64 + t) * DIN + d0 + c4;
            float4 r = *(const float4*)&inp[a];
            v.x += r.x; v.y += r.y; v.z += r.z; v.w += r.w;
            *(float4*)&out[a] = v;
        }
        __syncthreads();
    }
}

// ---------------------------------------------------------------
// prepass kernels: rna-to-tf32 rounding (device globals only in device code)
// ---------------------------------------------------------------
__global__ void k_rnd_inp(const float* __restrict__ s) {
    size_t i = (size_t)blockIdx.x * 256 + threadIdx.x;
    float4 v = ((const float4*)s)[i];
    v.x = rna(v.x); v.y = rna(v.y); v.z = rna(v.z); v.w = rna(v.w);
    ((float4*)g_ir)[i] = v;
}
__global__ void k_rnd_w1(const float* __restrict__ s) {
    size_t i = (size_t)blockIdx.x * 256 + threadIdx.x;
    float4 v = ((const float4*)s)[i];
    v.x = rna(v.x); v.y = rna(v.y); v.z = rna(v.z); v.w = rna(v.w);
    ((float4*)g_w1r)[i] = v;
}
__global__ void k_rnd_pw(const float* __restrict__ s) {
    size_t i = (size_t)blockIdx.x * 256 + threadIdx.x;
    float4 v = ((const float4*)s)[i];
    v.x = rna(v.x); v.y = rna(v.y); v.z = rna(v.z); v.w = rna(v.w);
    ((float4*)g_pwr)[i] = v;
}
// w2s[b][d][o] = rna(w2[d,o] * pinv[b,o]);  grid (384, Bn)
__global__ void k_w2s(const float* __restrict__ w2w) {
    int b = blockIdx.y;
    size_t li = (size_t)blockIdx.x * 256 + threadIdx.x;   // over DIN*H2n/4
    size_t i4 = li * 4;
    int o = (int)(i4 & (H2n - 1));
    int d = (int)(i4 >> 10);
    float4 v = *(const float4*)&w2w[(size_t)d * H2n + o];
    float4 sc = *(const float4*)&g_pinv[b * H2n + o];
    float4 r;
    r.x = rna(v.x * sc.x); r.y = rna(v.y * sc.y);
    r.z = rna(v.z * sc.z); r.w = rna(v.w * sc.w);
    *(float4*)&g_w2s[((size_t)b * DIN + d) * H2n + o] = r;
}

// ---------------------------------------------------------------
// normalized depthwise weights
// ---------------------------------------------------------------
__global__ void k_dwn(const float* __restrict__ dw, const float* __restrict__ dg) {
    int b = blockIdx.x;
    __shared__ float red[256];
    __shared__ float nrm[KW];
    int tid = threadIdx.x;
    float acc[KW];
#pragma unroll
    for (int k = 0; k < KW; k++) acc[k] = 0.f;
    for (int c = tid; c < H1n; c += 256) {
        const float* p = dw + ((size_t)b * H1n + c) * KW;
#pragma unroll
        for (int k = 0; k < KW; k++) { float v = p[k]; acc[k] += v * v; }
    }
    for (int k = 0; k < KW; k++) {
        red[tid] = acc[k];
        __syncthreads();
        for (int s = 128; s > 0; s >>= 1) {
            if (tid < s) red[tid] += red[tid + s];
            __syncthreads();
        }
        if (tid == 0) nrm[k] = fmaxf(sqrtf(red[0]), 1e-12f);
        __syncthreads();
    }
    for (int c = tid; c < H1n; c += 256) {
        float g = dg[b * H1n + c];
        const float* p = dw + ((size_t)b * H1n + c) * KW;
        float* q = g_dwn + ((size_t)b * H1n + c) * KW;
#pragma unroll
        for (int k = 0; k < KW; k++) q[k] = p[k] / nrm[k] * g;
    }
}

// ---------------------------------------------------------------
// g_pinv[b,o] = 1/||p_w[b,:,o]||   (from ORIGINAL pw)
// ---------------------------------------------------------------
__global__ void k_pinv(const float* __restrict__ pw) {
    int b = blockIdx.y;
    int o = blockIdx.x * 256 + threadIdx.x;
    const float* base = pw + (size_t)b * H1n * H2n + o;
    float acc = 0.f;
#pragma unroll 8
    for (int c = 0; c < H1n; c++) {
        float v = base[(size_t)c * H2n];
        acc += v * v;
    }
    g_pinv[b * H2n + o] = 1.0f / fmaxf(sqrtf(acc), 1e-12f);
}

// ---------------------------------------------------------------
// depthwise conv [t][c]: Y = rna(T * conv(X))
// grid (T/256, H1/32, B), 256 thr
// ---------------------------------------------------------------
__global__ void k_conv() {
    int b = blockIdx.z, c0 = blockIdx.y * 32, t0 = blockIdx.x * 256;
    __shared__ float xs[264][32];
    int tid = threadIdx.x;
    int c = tid & 31, tr = tid >> 5;
    const float* X = g_X + (size_t)b * Tn * H1n + c0;
    for (int i = tr; i < 264; i += 8) {
        int t = t0 + i - 4;
        xs[i][c] = (t >= 0 && t < Tn) ? X[(size_t)t * H1n + c] : 0.f;
    }
    float w[KW];
    const float* wp = g_dwn + ((size_t)b * H1n + c0 + c) * KW;
#pragma unroll
    for (int k = 0; k < KW; k++) w[k] = wp[k];
    __syncthreads();
    size_t ybase = ((size_t)b * Tn + t0) * H1n + c0;
    for (int j = 0; j < 32; j++) {
        int t = tr * 32 + j;
        float s = 0.f;
#pragma unroll
        for (int k = 0; k < KW; k++) s += xs[t + k][c] * w[k];
        g_Y[ybase + (size_t)t * H1n + c] = rna(s * (float)Tn);
    }
}

// ---------------------------------------------------------------
// bias2[b,d] = sum_c M[b,d,c]*d_b[b,c] + sum_o w2[d,o]*p_b[b,o] + w2b[d]
// ---------------------------------------------------------------
__global__ void k_bias2(const float* __restrict__ db, const float* __restrict__ w2w,
                        const float* __restrict__ pb, const float* __restrict__ w2b) {
    int d = blockIdx.x, b = blockIdx.y;
    int tid = threadIdx.x;
    const float* Mrow = g_M + ((size_t)b * DIN + d) * H1n;
    const float* dbp = db + b * H1n;
    float acc = 0.f;
    for (int c = tid; c < H1n; c += 256) acc += Mrow[c] * dbp[c];
    const float* w2r = w2w + (size_t)d * H2n;
    const float* pbp = pb + b * H2n;
    for (int o = tid; o < H2n; o += 256) acc += w2r[o] * pbp[o];
    __shared__ float red[256];
    red[tid] = acc;
    __syncthreads();
    for (int s = 128; s > 0; s >>= 1) {
        if (tid < s) red[tid] += red[tid + s];
        __syncthreads();
    }
    if (tid == 0) g_bias2[b * DIN + d] = red[0] + w2b[d];
}

// ---------------------------------------------------------------
extern "C" void kernel_launch(void* const* d_in, const int* in_sizes, int n_in,
                              void* d_out, int out_size) {
    const float* inp = (const float*)d_in[0];   // [B,T,DIN]
    const float* dw  = (const float*)d_in[1];   // [B,H1,1,K]
    const float* dg  = (const float*)d_in[2];   // [B,H1]
    const float* db  = (const float*)d_in[3];   // [B,H1]
    const float* pw  = (const float*)d_in[4];   // [B,H1,H2,1]
    const float* pg  = (const float*)d_in[5];   // [B,H1]
    const float* pb  = (const float*)d_in[6];   // [B,H2]
    const float* w1w = (const float*)d_in[7];   // [H1,DIN]
    const float* w1b = (const float*)d_in[8];   // [H1]
    const float* w2w = (const float*)d_in[9];   // [DIN,H2]
    const float* w2b = (const float*)d_in[10];  // [DIN]
    float* out = (float*)d_out;                 // [B,T,DIN]
    (void)in_sizes; (void)n_in; (void)out_size;

    k_dwn<<<Bn, 256>>>(dw, dg);
    k_pinv<<<dim3(H2n / 256, Bn), 256>>>(pw);

    unsigned nb_inp = (unsigned)((size_t)Bn * Tn * DIN / 4 / 256);   // 6144
    unsigned nb_w1  = (unsigned)((size_t)H1n * DIN / 4 / 256);       // 384
    unsigned nb_pw  = (unsigned)((size_t)Bn * H1n * H2n / 4 / 256);  // 16384
    unsigned nb_w2s = (unsigned)((size_t)DIN * H2n / 4 / 256);       // 384
    k_rnd_inp<<<nb_inp, 256>>>(inp);
    k_rnd_w1<<<nb_w1, 256>>>(w1w);
    k_rnd_pw<<<nb_pw, 256>>>(pw);
    k_w2s<<<dim3(nb_w2s, Bn), 256>>>(w2w);

    k_mm1<<<dim3(H1n / 128, Tn / 128, Bn), 256>>>(w1b);
    k_conv<<<dim3(Tn / 256, H1n / 32, Bn), 256>>>();
    k_mmC<<<dim3(H1n / 128, DIN / 128, Bn), 256>>>(pg);
    k_bias2<<<dim3(DIN, Bn), 256>>>(db, w2w, pb, w2b);
    k_mmE<<<dim3(DIN / 128, Tn / 128, Bn), 256>>>(inp, out);
}

// round 12
// speedup vs baseline: 2.9117x; 1.2101x over previous
#include <cuda_runtime.h>
#include <cuda_bf16.h>
#include <math.h>
#include <stdint.h>

#define Bn   16
#define Tn   1024
#define DIN  384
#define H1n  1024
#define H2n  1024
#define KW   9

// -------- persistent scratch (device globals; referenced ONLY in device code) ----
__device__ float g_X[(size_t)Bn * Tn * H1n];      // mish(GEMM1): [b][t][c]
__device__ float g_Y[(size_t)Bn * Tn * H1n];      // conv out (tf32-rounded): [b][t][c]
__device__ float g_ir[(size_t)Bn * Tn * DIN];     // rna(input) [b][t][k]
__device__ float g_w1r[(size_t)H1n * DIN];        // rna(w1)    [c][k]
__device__ float g_pwr[(size_t)Bn * H1n * H2n];   // rna(pw)    [b][c][o]
__device__ float g_w2s[(size_t)Bn * DIN * H2n];   // rna(w2*pinv) [b][d][o]
__device__ float g_M[(size_t)Bn * DIN * H1n];     // M (tf32-rounded) [b][d][c]
__device__ float g_dwn[Bn * H1n * KW];
__device__ float g_pinv[Bn * H2n];
__device__ float g_bias2[Bn * DIN];

// ================= base-family PTX helpers =================
__device__ __forceinline__ uint32_t smem_to_u32(const void* p) {
    uint32_t a;
    asm("{ .reg .u64 t; cvta.to.shared.u64 t, %1; cvt.u32.u64 %0, t; }" : "=r"(a) : "l"(p));
    return a;
}
__device__ __forceinline__ void cp16(uint32_t dst, const void* src) {
    asm volatile("cp.async.cg.shared.global [%0], [%1], 16;" :: "r"(dst), "l"(src));
}
__device__ __forceinline__ void cp_commit() {
    asm volatile("cp.async.commit_group;" ::: "memory");
}
__device__ __forceinline__ void mma_tf32(float (&c)[4], const uint32_t (&a)[4],
                                         const uint32_t (&b)[2]) {
    asm volatile(
        "mma.sync.aligned.m16n8k8.row.col.f32.tf32.tf32.f32 "
        "{%0,%1,%2,%3}, {%4,%5,%6,%7}, {%8,%9}, {%0,%1,%2,%3};"
        : "+f"(c[0]), "+f"(c[1]), "+f"(c[2]), "+f"(c[3])
        : "r"(a[0]), "r"(a[1]), "r"(a[2]), "r"(a[3]), "r"(b[0]), "r"(b[1]));
}
// round-to-nearest tf32 (unbiased), returned as fp32 bit pattern
__device__ __forceinline__ float rna(float f) {
    uint32_t r;
    asm("cvt.rna.tf32.f32 %0, %1;" : "=r"(r) : "f"(f));
    return __uint_as_float(r);
}

// ================= GEMM tile geometry =================
// CTA tile 128x128, K-tile 32 fp32(tf32), 2-stage cp.async pipeline,
// 64KB DYNAMIC smem (opt-in). Rows are 128B (32 words) with XOR chunk swizzle
// (chunk ^= row&7): fragment LDS banks 4*(c^g)+tig all distinct; cp.async
// stores conflict-free per phase.
#define PLANE_W  4096u                 // 128 rows * 32 words
#define STAGE_W  (2u * PLANE_W)        // A, B
#define GSMEM_B  65536u                // 2 stages * 32KB

// word index of element (row r, chunk c, word-in-chunk w) with swizzle
__device__ __forceinline__ uint32_t swi(uint32_t r, uint32_t c, uint32_t w) {
    return r * 32u + ((c ^ (r & 7u)) << 2) + w;
}

__device__ __forceinline__ void load_stage(uint32_t sb, int buf,
        const float* __restrict__ A, int lda,
        const float* __restrict__ B, int ldb,
        int k0, int tid) {
    uint32_t base = sb + (uint32_t)buf * (STAGE_W * 4u);
#pragma unroll
    for (int j = 0; j < 8; j++) {
        int cid = tid + j * 256;            // 0..2047
        int plane = cid >> 10;              // 0:A 1:B
        int idx = cid & 1023;
        int r = idx >> 3, q = idx & 7;      // row 0..127, chunk 0..7
        uint32_t d = base + (uint32_t)plane * (PLANE_W * 4u)
                   + (uint32_t)r * 128u + (uint32_t)((q ^ (r & 7)) << 4);
        const float* s = (plane ? B + (size_t)r * ldb : A + (size_t)r * lda) + k0 + q * 4;
        cp16(d, s);
    }
}

__device__ __forceinline__ void compute_stage(const uint32_t* __restrict__ W, int buf,
                                              int wm, int wn, int lane,
                                              float acc[4][4][4]) {
    const uint32_t* Aw = W + (uint32_t)buf * STAGE_W;
    const uint32_t* Bw = Aw + PLANE_W;
    uint32_t g = lane >> 2, tig = lane & 3;
#pragma unroll
    for (int ks = 0; ks < 4; ks++) {
        uint32_t c0 = 2 * ks, c1 = 2 * ks + 1;
        uint32_t a[4][4], bf[4][2];
#pragma unroll
        for (int mt = 0; mt < 4; mt++) {
            uint32_t r1 = (uint32_t)(wm * 64 + mt * 16) + g;
            uint32_t r2 = r1 + 8;
            a[mt][0] = Aw[swi(r1, c0, tig)];
            a[mt][1] = Aw[swi(r2, c0, tig)];
            a[mt][2] = Aw[swi(r1, c1, tig)];
            a[mt][3] = Aw[swi(r2, c1, tig)];
        }
#pragma unroll
        for (int nt = 0; nt < 4; nt++) {
            uint32_t r = (uint32_t)(wn * 32 + nt * 8) + g;
            bf[nt][0] = Bw[swi(r, c0, tig)];
            bf[nt][1] = Bw[swi(r, c1, tig)];
        }
#pragma unroll
        for (int mt = 0; mt < 4; mt++)
#pragma unroll
            for (int nt = 0; nt < 4; nt++)
                mma_tf32(acc[mt][nt], a[mt], bf[nt]);
    }
}

// Single barrier per iteration; next-stage cp.async issued AFTER the sync.
__device__ __forceinline__ void gemm_main(const uint32_t* W, uint32_t sb,
        const float* A, int lda, const float* B, int ldb,
        int kiters, float acc[4][4][4], int tid) {
    int wid = tid >> 5, lane = tid & 31, wm = wid & 1, wn = wid >> 1;
#pragma unroll
    for (int i = 0; i < 4; i++)
#pragma unroll
        for (int j = 0; j < 4; j++)
#pragma unroll
            for (int k = 0; k < 4; k++) acc[i][j][k] = 0.f;

    load_stage(sb, 0, A, lda, B, ldb, 0, tid);
    cp_commit();
    for (int it = 0; it < kiters; it++) {
        asm volatile("cp.async.wait_group 0;" ::: "memory");
        __syncthreads();
        if (it + 1 < kiters) {
            load_stage(sb, (it + 1) & 1, A, lda, B, ldb, (it + 1) * 32, tid);
            cp_commit();
        }
        compute_stage(W, it & 1, wm, wn, lane, acc);
    }
    __syncthreads();   // smem about to be reused as epilogue stage
}

// mish(x) = x*(u^2+2u)/(u^2+2u+2), u=e^x
__device__ __forceinline__ float mishf(float x) {
    if (x > 15.f) return x;
    float u = expf(x);
    float t = u * (u + 2.f);
    return x * __fdividef(t, t + 2.f);
}

// ---------------------------------------------------------------
// GEMM1: D[c,t] = sum_k w1r[c,k]*ir[b,t,k]; X[b][t][c] = mish(D + w1b[c])
// grid (H1/128, T/128, B), 256 thr
// ---------------------------------------------------------------
__global__ void __launch_bounds__(256, 2)
k_mm1(const float* __restrict__ w1b) {
    extern __shared__ __align__(16) char smem[];
    uint32_t sb = smem_to_u32(smem);
    const uint32_t* W = (const uint32_t*)smem;
    int tid = threadIdx.x;
    int b = blockIdx.z, c0 = blockIdx.x * 128, t0 = blockIdx.y * 128;
    float acc[4][4][4];
    gemm_main(W, sb,
              g_w1r + (size_t)c0 * DIN, DIN,
              g_ir + ((size_t)b * Tn + t0) * DIN, DIN,
              DIN / 32, acc, tid);
    int wid = tid >> 5, lane = tid & 31, wm = wid & 1, wn = wid >> 1;
    int g = lane >> 2, tig = lane & 3;
    float* stage = (float*)smem;                        // [64][132]
    for (int h = 0; h < 2; h++) {
        if ((wn >> 1) == h) {
            int tl0 = (wn & 1) * 32;
#pragma unroll
            for (int mt = 0; mt < 4; mt++) {
                int c = wm * 64 + mt * 16 + g;
                float b0 = w1b[c0 + c], b1 = w1b[c0 + c + 8];
#pragma unroll
                for (int nt = 0; nt < 4; nt++) {
                    int t = tl0 + nt * 8 + tig * 2;
                    stage[t * 132 + c]           = mishf(acc[mt][nt][0] + b0);
                    stage[(t + 1) * 132 + c]     = mishf(acc[mt][nt][1] + b0);
                    stage[t * 132 + c + 8]       = mishf(acc[mt][nt][2] + b1);
                    stage[(t + 1) * 132 + c + 8] = mishf(acc[mt][nt][3] + b1);
                }
            }
        }
        __syncthreads();
#pragma unroll
        for (int j = 0; j < 8; j++) {
            int idx = tid + j * 256;
            int t = idx >> 5, c4 = (idx & 31) * 4;
            float4 v = *(const float4*)&stage[t * 132 + c4];
            *(float4*)&g_X[((size_t)b * Tn + t0 + h * 64 + t) * H1n + c0 + c4] = v;
        }
        __syncthreads();
    }
}

// ---------------------------------------------------------------
// GEMMC: D[c,d] = sum_o pwr[b,c,o]*w2s[b,d,o]; M[b][d][c] = rna(D*pg[b,c])
// grid (H1/128, DIN/128, B); M-dim = c, N-dim = d
// ---------------------------------------------------------------
__global__ void __launch_bounds__(256, 2)
k_mmC(const float* __restrict__ pg) {
    extern __shared__ __align__(16) char smem[];
    uint32_t sb = smem_to_u32(smem);
    const uint32_t* W = (const uint32_t*)smem;
    int tid = threadIdx.x;
    int b = blockIdx.z, c0 = blockIdx.x * 128, d0 = blockIdx.y * 128;
    float acc[4][4][4];
    gemm_main(W, sb,
              g_pwr + ((size_t)b * H1n + c0) * H2n, H2n,
              g_w2s + ((size_t)b * DIN + d0) * H2n, H2n,
              H2n / 32, acc, tid);
    int wid = tid >> 5, lane = tid & 31, wm = wid & 1, wn = wid >> 1;
    int g = lane >> 2, tig = lane & 3;
    float* stage = (float*)smem;                        // [64][132] (rows = d)
    for (int h = 0; h < 2; h++) {
        if ((wn >> 1) == h) {
            int dl0 = (wn & 1) * 32;
#pragma unroll
            for (int mt = 0; mt < 4; mt++) {
                int c = wm * 64 + mt * 16 + g;
                float p0 = pg[b * H1n + c0 + c], p1 = pg[b * H1n + c0 + c + 8];
#pragma unroll
                for (int nt = 0; nt < 4; nt++) {
                    int d = dl0 + nt * 8 + tig * 2;
                    stage[d * 132 + c]           = acc[mt][nt][0] * p0;
                    stage[(d + 1) * 132 + c]     = acc[mt][nt][1] * p0;
                    stage[d * 132 + c + 8]       = acc[mt][nt][2] * p1;
                    stage[(d + 1) * 132 + c + 8] = acc[mt][nt][3] * p1;
                }
            }
        }
        __syncthreads();
#pragma unroll
        for (int j = 0; j < 8; j++) {
            int idx = tid + j * 256;
            int d = idx >> 5, c4 = (idx & 31) * 4;
            float4 v = *(const float4*)&stage[d * 132 + c4];
            v.x = rna(v.x); v.y = rna(v.y); v.z = rna(v.z); v.w = rna(v.w);
            *(float4*)&g_M[((size_t)b * DIN + d0 + h * 64 + d) * H1n + c0 + c4] = v;
        }
        __syncthreads();
    }
}

// ---------------------------------------------------------------
// GEMME: D[d,t] = sum_c M[b,d,c]*Y[b,t,c]; out = D + bias2 + residual
// grid (DIN/128, T/128, B); M-dim = d, N-dim = t
// ---------------------------------------------------------------
__global__ void __launch_bounds__(256, 2)
k_mmE(const float* __restrict__ inp, float* __restrict__ out) {
    extern __shared__ __align__(16) char smem[];
    uint32_t sb = smem_to_u32(smem);
    const uint32_t* W = (const uint32_t*)smem;
    int tid = threadIdx.x;
    int b = blockIdx.z, d0 = blockIdx.x * 128, t0 = blockIdx.y * 128;
    float acc[4][4][4];
    gemm_main(W, sb,
              g_M + ((size_t)b * DIN + d0) * H1n, H1n,
              g_Y + ((size_t)b * Tn + t0) * H1n, H1n,
              H1n / 32, acc, tid);
    int wid = tid >> 5, lane = tid & 31, wm = wid & 1, wn = wid >> 1;
    int g = lane >> 2, tig = lane & 3;
    float* stage = (float*)smem;                        // [64][132] (rows = t)
    for (int h = 0; h < 2; h++) {
        if ((wn >> 1) == h) {
            int tl0 = (wn & 1) * 32;
#pragma unroll
            for (int mt = 0; mt < 4; mt++) {
                int d = wm * 64 + mt * 16 + g;
                float b0 = g_bias2[b * DIN + d0 + d], b1 = g_bias2[b * DIN + d0 + d + 8];
#pragma unroll
                for (int nt = 0; nt < 4; nt++) {
                    int t = tl0 + nt * 8 + tig * 2;
                    stage[t * 132 + d]           = acc[mt][nt][0] + b0;
                    stage[(t + 1) * 132 + d]     = acc[mt][nt][1] + b0;
                    stage[t * 132 + d + 8]       = acc[mt][nt][2] + b1;
                    stage[(t + 1) * 132 + d + 8] = acc[mt][nt][3] + b1;
                }
            }
        }
        __syncthreads();
#pragma unroll
        for (int j = 0; j < 8; j++) {
            int idx = tid + j * 256;
            int t = idx >> 5, c4 = (idx & 31) * 4;
            float4 v = *(const float4*)&stage[t * 132 + c4];
            size_t a = ((size_t)b * Tn + t0 + h * 64 + t) * DIN + d0 + c4;
            float4 r = *(const float4*)&inp[a];
            v.x += r.x; v.y += r.y; v.z += r.z; v.w += r.w;
            *(float4*)&out[a] = v;
        }
        __syncthreads();
    }
}

// ---------------------------------------------------------------
// prepass kernels: rna-to-tf32 rounding
// ---------------------------------------------------------------
__global__ void k_rnd_inp(const float* __restrict__ s) {
    size_t i = (size_t)blockIdx.x * 256 + threadIdx.x;
    float4 v = ((const float4*)s)[i];
    v.x = rna(v.x); v.y = rna(v.y); v.z = rna(v.z); v.w = rna(v.w);
    ((float4*)g_ir)[i] = v;
}
__global__ void k_rnd_w1(const float* __restrict__ s) {
    size_t i = (size_t)blockIdx.x * 256 + threadIdx.x;
    float4 v = ((const float4*)s)[i];
    v.x = rna(v.x); v.y = rna(v.y); v.z = rna(v.z); v.w = rna(v.w);
    ((float4*)g_w1r)[i] = v;
}
__global__ void k_rnd_pw(const float* __restrict__ s) {
    size_t i = (size_t)blockIdx.x * 256 + threadIdx.x;
    float4 v = ((const float4*)s)[i];
    v.x = rna(v.x); v.y = rna(v.y); v.z = rna(v.z); v.w = rna(v.w);
    ((float4*)g_pwr)[i] = v;
}
// w2s[b][d][o] = rna(w2[d,o] * pinv[b,o]);  grid (384, Bn)
__global__ void k_w2s(const float* __restrict__ w2w) {
    int b = blockIdx.y;
    size_t li = (size_t)blockIdx.x * 256 + threadIdx.x;   // over DIN*H2n/4
    size_t i4 = li * 4;
    int o = (int)(i4 & (H2n - 1));
    int d = (int)(i4 >> 10);
    float4 v = *(const float4*)&w2w[(size_t)d * H2n + o];
    float4 sc = *(const float4*)&g_pinv[b * H2n + o];
    float4 r;
    r.x = rna(v.x * sc.x); r.y = rna(v.y * sc.y);
    r.z = rna(v.z * sc.z); r.w = rna(v.w * sc.w);
    *(float4*)&g_w2s[((size_t)b * DIN + d) * H2n + o] = r;
}

// ---------------------------------------------------------------
// normalized depthwise weights
// ---------------------------------------------------------------
__global__ void k_dwn(const float* __restrict__ dw, const float* __restrict__ dg) {
    int b = blockIdx.x;
    __shared__ float red[256];
    __shared__ float nrm[KW];
    int tid = threadIdx.x;
    float acc[KW];
#pragma unroll
    for (int k = 0; k < KW; k++) acc[k] = 0.f;
    for (int c = tid; c < H1n; c += 256) {
        const float* p = dw + ((size_t)b * H1n + c) * KW;
#pragma unroll
        for (int k = 0; k < KW; k++) { float v = p[k]; acc[k] += v * v; }
    }
    for (int k = 0; k < KW; k++) {
        red[tid] = acc[k];
        __syncthreads();
        for (int s = 128; s > 0; s >>= 1) {
            if (tid < s) red[tid] += red[tid + s];
            __syncthreads();
        }
        if (tid == 0) nrm[k] = fmaxf(sqrtf(red[0]), 1e-12f);
        __syncthreads();
    }
    for (int c = tid; c < H1n; c += 256) {
        float g = dg[b * H1n + c];
        const float* p = dw + ((size_t)b * H1n + c) * KW;
        float* q = g_dwn + ((size_t)b * H1n + c) * KW;
#pragma unroll
        for (int k = 0; k < KW; k++) q[k] = p[k] / nrm[k] * g;
    }
}

// ---------------------------------------------------------------
// g_pinv[b,o] = 1/||p_w[b,:,o]||   (from ORIGINAL pw)
// ---------------------------------------------------------------
__global__ void k_pinv(const float* __restrict__ pw) {
    int b = blockIdx.y;
    int o = blockIdx.x * 256 + threadIdx.x;
    const float* base = pw + (size_t)b * H1n * H2n + o;
    float acc = 0.f;
#pragma unroll 8
    for (int c = 0; c < H1n; c++) {
        float v = base[(size_t)c * H2n];
        acc += v * v;
    }
    g_pinv[b * H2n + o] = 1.0f / fmaxf(sqrtf(acc), 1e-12f);
}

// ---------------------------------------------------------------
// depthwise conv [t][c]: Y = rna(T * conv(X))
// grid (T/256, H1/32, B), 256 thr
// ---------------------------------------------------------------
__global__ void k_conv() {
    int b = blockIdx.z, c0 = blockIdx.y * 32, t0 = blockIdx.x * 256;
    __shared__ float xs[264][32];
    int tid = threadIdx.x;
    int c = tid & 31, tr = tid >> 5;
    const float* X = g_X + (size_t)b * Tn * H1n + c0;
    for (int i = tr; i < 264; i += 8) {
        int t = t0 + i - 4;
        xs[i][c] = (t >= 0 && t < Tn) ? X[(size_t)t * H1n + c] : 0.f;
    }
    float w[KW];
    const float* wp = g_dwn + ((size_t)b * H1n + c0 + c) * KW;
#pragma unroll
    for (int k = 0; k < KW; k++) w[k] = wp[k];
    __syncthreads();
    size_t ybase = ((size_t)b * Tn + t0) * H1n + c0;
    for (int j = 0; j < 32; j++) {
        int t = tr * 32 + j;
        float s = 0.f;
#pragma unroll
        for (int k = 0; k < KW; k++) s += xs[t + k][c] * w[k];
        g_Y[ybase + (size_t)t * H1n + c] = rna(s * (float)Tn);
    }
}

// ---------------------------------------------------------------
// bias2[b,d] = sum_c M[b,d,c]*d_b[b,c] + sum_o w2[d,o]*p_b[b,o] + w2b[d]
// ---------------------------------------------------------------
__global__ void k_bias2(const float* __restrict__ db, const float* __restrict__ w2w,
                        const float* __restrict__ pb, const float* __restrict__ w2b) {
    int d = blockIdx.x, b = blockIdx.y;
    int tid = threadIdx.x;
    const float* Mrow = g_M + ((size_t)b * DIN + d) * H1n;
    const float* dbp = db + b * H1n;
    float acc = 0.f;
    for (int c = tid; c < H1n; c += 256) acc += Mrow[c] * dbp[c];
    const float* w2r = w2w + (size_t)d * H2n;
    const float* pbp = pb + b * H2n;
    for (int o = tid; o < H2n; o += 256) acc += w2r[o] * pbp[o];
    __shared__ float red[256];
    red[tid] = acc;
    __syncthreads();
    for (int s = 128; s > 0; s >>= 1) {
        if (tid < s) red[tid] += red[tid + s];
        __syncthreads();
    }
    if (tid == 0) g_bias2[b * DIN + d] = red[0] + w2b[d];
}

// ---------------------------------------------------------------
extern "C" void kernel_launch(void* const* d_in, const int* in_sizes, int n_in,
                              void* d_out, int out_size) {
    const float* inp = (const float*)d_in[0];   // [B,T,DIN]
    const float* dw  = (const float*)d_in[1];   // [B,H1,1,K]
    const float* dg  = (const float*)d_in[2];   // [B,H1]
    const float* db  = (const float*)d_in[3];   // [B,H1]
    const float* pw  = (const float*)d_in[4];   // [B,H1,H2,1]
    const float* pg  = (const float*)d_in[5];   // [B,H1]
    const float* pb  = (const float*)d_in[6];   // [B,H2]
    const float* w1w = (const float*)d_in[7];   // [H1,DIN]
    const float* w1b = (const float*)d_in[8];   // [H1]
    const float* w2w = (const float*)d_in[9];   // [DIN,H2]
    const float* w2b = (const float*)d_in[10];  // [DIN]
    float* out = (float*)d_out;                 // [B,T,DIN]
    (void)in_sizes; (void)n_in; (void)out_size;

    cudaFuncSetAttribute(k_mm1, cudaFuncAttributeMaxDynamicSharedMemorySize, GSMEM_B);
    cudaFuncSetAttribute(k_mmC, cudaFuncAttributeMaxDynamicSharedMemorySize, GSMEM_B);
    cudaFuncSetAttribute(k_mmE, cudaFuncAttributeMaxDynamicSharedMemorySize, GSMEM_B);

    k_dwn<<<Bn, 256>>>(dw, dg);
    k_pinv<<<dim3(H2n / 256, Bn), 256>>>(pw);

    unsigned nb_inp = (unsigned)((size_t)Bn * Tn * DIN / 4 / 256);   // 6144
    unsigned nb_w1  = (unsigned)((size_t)H1n * DIN / 4 / 256);       // 384
    unsigned nb_pw  = (unsigned)((size_t)Bn * H1n * H2n / 4 / 256);  // 16384
    unsigned nb_w2s = (unsigned)((size_t)DIN * H2n / 4 / 256);       // 384
    k_rnd_inp<<<nb_inp, 256>>>(inp);
    k_rnd_w1<<<nb_w1, 256>>>(w1w);
    k_rnd_pw<<<nb_pw, 256>>>(pw);
    k_w2s<<<dim3(nb_w2s, Bn), 256>>>(w2w);

    k_mm1<<<dim3(H1n / 128, Tn / 128, Bn), 256, GSMEM_B>>>(w1b);
    k_conv<<<dim3(Tn / 256, H1n / 32, Bn), 256>>>();
    k_mmC<<<dim3(H1n / 128, DIN / 128, Bn), 256, GSMEM_B>>>(pg);
    k_bias2<<<dim3(DIN, Bn), 256>>>(db, w2w, pb, w2b);
    k_mmE<<<dim3(DIN / 128, Tn / 128, Bn), 256, GSMEM_B>>>(inp, out);
}

// round 17
// speedup vs baseline: 2.9660x; 1.0187x over previous
#include <cuda_runtime.h>
#include <cuda_bf16.h>
#include <math.h>
#include <stdint.h>

#define Bn   16
#define Tn   1024
#define DIN  384
#define H1n  1024
#define H2n  1024
#define KW   9

// -------- persistent scratch (device globals; referenced ONLY in device code) ----
__device__ float g_X[(size_t)Bn * Tn * H1n];      // mish(GEMM1): [b][t][c]
__device__ float g_Y[(size_t)Bn * Tn * H1n];      // conv out (tf32-rounded): [b][t][c]
__device__ float g_ir[(size_t)Bn * Tn * DIN];     // rna(input) [b][t][k]
__device__ float g_w1r[(size_t)H1n * DIN];        // rna(w1)    [c][k]
__device__ float g_pwr[(size_t)Bn * H1n * H2n];   // rna(pw)    [b][c][o]
__device__ float g_w2s[(size_t)Bn * DIN * H2n];   // rna(w2*pinv) [b][d][o]
__device__ float g_M[(size_t)Bn * DIN * H1n];     // M (tf32-rounded) [b][d][c]
__device__ float g_dwn[Bn * H1n * KW];
__device__ float g_pinv[Bn * H2n];
__device__ float g_bias2[Bn * DIN];

// ================= base-family PTX helpers =================
__device__ __forceinline__ uint32_t smem_to_u32(const void* p) {
    uint32_t a;
    asm("{ .reg .u64 t; cvta.to.shared.u64 t, %1; cvt.u32.u64 %0, t; }" : "=r"(a) : "l"(p));
    return a;
}
__device__ __forceinline__ void cp16(uint32_t dst, const void* src) {
    asm volatile("cp.async.cg.shared.global [%0], [%1], 16;" :: "r"(dst), "l"(src));
}
__device__ __forceinline__ void cp_commit() {
    asm volatile("cp.async.commit_group;" ::: "memory");
}
__device__ __forceinline__ void mma_tf32(float (&c)[4], const uint32_t (&a)[4],
                                         const uint32_t (&b)[2]) {
    asm volatile(
        "mma.sync.aligned.m16n8k8.row.col.f32.tf32.tf32.f32 "
        "{%0,%1,%2,%3}, {%4,%5,%6,%7}, {%8,%9}, {%0,%1,%2,%3};"
        : "+f"(c[0]), "+f"(c[1]), "+f"(c[2]), "+f"(c[3])
        : "r"(a[0]), "r"(a[1]), "r"(a[2]), "r"(a[3]), "r"(b[0]), "r"(b[1]));
}
// round-to-nearest tf32 (unbiased), returned as fp32 bit pattern
__device__ __forceinline__ float rna(float f) {
    uint32_t r;
    asm("cvt.rna.tf32.f32 %0, %1;" : "=r"(r) : "f"(f));
    return __uint_as_float(r);
}

// ================= GEMM tile geometry =================
// CTA tile 128x128, K-tile 32 fp32(tf32), 3-stage cp.async pipeline,
// 96KB DYNAMIC smem (opt-in; 2 CTAs/SM = 192KB <= 228KB). Rows are 128B
// (32 words) with XOR chunk swizzle (chunk ^= row&7): fragment LDS banks
// 4*(c^g)+tig all distinct; cp.async stores conflict-free per phase.
#define PLANE_W  4096u                 // 128 rows * 32 words
#define STAGE_W  (2u * PLANE_W)        // A, B
#define STAGES   3u
#define GSMEM_B  (STAGES * STAGE_W * 4u)   // 98304

// word index of element (row r, chunk c, word-in-chunk w) with swizzle
__device__ __forceinline__ uint32_t swi(uint32_t r, uint32_t c, uint32_t w) {
    return r * 32u + ((c ^ (r & 7u)) << 2) + w;
}

__device__ __forceinline__ void load_stage(uint32_t sb, uint32_t buf,
        const float* __restrict__ A, int lda,
        const float* __restrict__ B, int ldb,
        int k0, int tid) {
    uint32_t base = sb + buf * (STAGE_W * 4u);
#pragma unroll
    for (int j = 0; j < 8; j++) {
        int cid = tid + j * 256;            // 0..2047
        int plane = cid >> 10;              // 0:A 1:B
        int idx = cid & 1023;
        int r = idx >> 3, q = idx & 7;      // row 0..127, chunk 0..7
        uint32_t d = base + (uint32_t)plane * (PLANE_W * 4u)
                   + (uint32_t)r * 128u + (uint32_t)((q ^ (r & 7)) << 4);
        const float* s = (plane ? B + (size_t)r * ldb : A + (size_t)r * lda) + k0 + q * 4;
        cp16(d, s);
    }
}

__device__ __forceinline__ void compute_stage(const uint32_t* __restrict__ W, uint32_t buf,
                                              int wm, int wn, int lane,
                                              float acc[4][4][4]) {
    const uint32_t* Aw = W + buf * STAGE_W;
    const uint32_t* Bw = Aw + PLANE_W;
    uint32_t g = lane >> 2, tig = lane & 3;
#pragma unroll
    for (int ks = 0; ks < 4; ks++) {
        uint32_t c0 = 2 * ks, c1 = 2 * ks + 1;
        uint32_t a[4][4], bf[4][2];
#pragma unroll
        for (int mt = 0; mt < 4; mt++) {
            uint32_t r1 = (uint32_t)(wm * 64 + mt * 16) + g;
            uint32_t r2 = r1 + 8;
            a[mt][0] = Aw[swi(r1, c0, tig)];
            a[mt][1] = Aw[swi(r2, c0, tig)];
            a[mt][2] = Aw[swi(r1, c1, tig)];
            a[mt][3] = Aw[swi(r2, c1, tig)];
        }
#pragma unroll
        for (int nt = 0; nt < 4; nt++) {
            uint32_t r = (uint32_t)(wn * 32 + nt * 8) + g;
            bf[nt][0] = Bw[swi(r, c0, tig)];
            bf[nt][1] = Bw[swi(r, c1, tig)];
        }
#pragma unroll
        for (int mt = 0; mt < 4; mt++)
#pragma unroll
            for (int nt = 0; nt < 4; nt++)
                mma_tf32(acc[mt][nt], a[mt], bf[nt]);
    }
}

// 3-stage pipeline, single barrier per iteration. At top of iter `it`,
// outstanding groups are {it, it+1(if issued)}; wait_group 1 drains group it
// (wait_group 0 on the last iteration). Load for it+2 is issued AFTER the
// sync, so the sync also protects buffer (it+2)%3 == (it-1)%3 against reuse.
__device__ __forceinline__ void gemm_main(const uint32_t* W, uint32_t sb,
        const float* A, int lda, const float* B, int ldb,
        int kiters, float acc[4][4][4], int tid) {
    int wid = tid >> 5, lane = tid & 31, wm = wid & 1, wn = wid >> 1;
#pragma unroll
    for (int i = 0; i < 4; i++)
#pragma unroll
        for (int j = 0; j < 4; j++)
#pragma unroll
            for (int k = 0; k < 4; k++) acc[i][j][k] = 0.f;

    load_stage(sb, 0, A, lda, B, ldb, 0, tid);
    cp_commit();
    load_stage(sb, 1, A, lda, B, ldb, 32, tid);
    cp_commit();
    uint32_t bc = 0, bn = 2;                 // compute buf, next-load buf
    for (int it = 0; it < kiters; it++) {
        if (it + 1 < kiters) {
            asm volatile("cp.async.wait_group 1;" ::: "memory");
        } else {
            asm volatile("cp.async.wait_group 0;" ::: "memory");
        }
        __syncthreads();
        if (it + 2 < kiters) {
            load_stage(sb, bn, A, lda, B, ldb, (it + 2) * 32, tid);
            cp_commit();
        }
        compute_stage(W, bc, wm, wn, lane, acc);
        if (++bc == 3) bc = 0;
        if (++bn == 3) bn = 0;
    }
    __syncthreads();   // smem about to be reused as epilogue stage
}

// mish(x) = x*(u^2+2u)/(u^2+2u+2), u=e^x
__device__ __forceinline__ float mishf(float x) {
    if (x > 15.f) return x;
    float u = expf(x);
    float t = u * (u + 2.f);
    return x * __fdividef(t, t + 2.f);
}

// ---------------------------------------------------------------
// GEMM1: D[c,t] = sum_k w1r[c,k]*ir[b,t,k]; X[b][t][c] = mish(D + w1b[c])
// grid (H1/128, T/128, B), 256 thr
// ---------------------------------------------------------------
__global__ void __launch_bounds__(256, 2)
k_mm1(const float* __restrict__ w1b) {
    extern __shared__ __align__(16) char smem[];
    uint32_t sb = smem_to_u32(smem);
    const uint32_t* W = (const uint32_t*)smem;
    int tid = threadIdx.x;
    int b = blockIdx.z, c0 = blockIdx.x * 128, t0 = blockIdx.y * 128;
    float acc[4][4][4];
    gemm_main(W, sb,
              g_w1r + (size_t)c0 * DIN, DIN,
              g_ir + ((size_t)b * Tn + t0) * DIN, DIN,
              DIN / 32, acc, tid);
    int wid = tid >> 5, lane = tid & 31, wm = wid & 1, wn = wid >> 1;
    int g = lane >> 2, tig = lane & 3;
    float* stage = (float*)smem;                        // [64][132]
    for (int h = 0; h < 2; h++) {
        if ((wn >> 1) == h) {
            int tl0 = (wn & 1) * 32;
#pragma unroll
            for (int mt = 0; mt < 4; mt++) {
                int c = wm * 64 + mt * 16 + g;
                float b0 = w1b[c0 + c], b1 = w1b[c0 + c + 8];
#pragma unroll
                for (int nt = 0; nt < 4; nt++) {
                    int t = tl0 + nt * 8 + tig * 2;
                    stage[t * 132 + c]           = mishf(acc[mt][nt][0] + b0);
                    stage[(t + 1) * 132 + c]     = mishf(acc[mt][nt][1] + b0);
                    stage[t * 132 + c + 8]       = mishf(acc[mt][nt][2] + b1);
                    stage[(t + 1) * 132 + c + 8] = mishf(acc[mt][nt][3] + b1);
                }
            }
        }
        __syncthreads();
#pragma unroll
        for (int j = 0; j < 8; j++) {
            int idx = tid + j * 256;
            int t = idx >> 5, c4 = (idx & 31) * 4;
            float4 v = *(const float4*)&stage[t * 132 + c4];
            *(float4*)&g_X[((size_t)b * Tn + t0 + h * 64 + t) * H1n + c0 + c4] = v;
        }
        __syncthreads();
    }
}

// ---------------------------------------------------------------
// GEMMC: D[c,d] = sum_o pwr[b,c,o]*w2s[b,d,o]; M[b][d][c] = rna(D*pg[b,c])
// grid (H1/128, DIN/128, B); M-dim = c, N-dim = d
// ---------------------------------------------------------------
__global__ void __launch_bounds__(256, 2)
k_mmC(const float* __restrict__ pg) {
    extern __shared__ __align__(16) char smem[];
    uint32_t sb = smem_to_u32(smem);
    const uint32_t* W = (const uint32_t*)smem;
    int tid = threadIdx.x;
    int b = blockIdx.z, c0 = blockIdx.x * 128, d0 = blockIdx.y * 128;
    float acc[4][4][4];
    gemm_main(W, sb,
              g_pwr + ((size_t)b * H1n + c0) * H2n, H2n,
              g_w2s + ((size_t)b * DIN + d0) * H2n, H2n,
              H2n / 32, acc, tid);
    int wid = tid >> 5, lane = tid & 31, wm = wid & 1, wn = wid >> 1;
    int g = lane >> 2, tig = lane & 3;
    float* stage = (float*)smem;                        // [64][132] (rows = d)
    for (int h = 0; h < 2; h++) {
        if ((wn >> 1) == h) {
            int dl0 = (wn & 1) * 32;
#pragma unroll
            for (int mt = 0; mt < 4; mt++) {
                int c = wm * 64 + mt * 16 + g;
                float p0 = pg[b * H1n + c0 + c], p1 = pg[b * H1n + c0 + c + 8];
#pragma unroll
                for (int nt = 0; nt < 4; nt++) {
                    int d = dl0 + nt * 8 + tig * 2;
                    stage[d * 132 + c]           = acc[mt][nt][0] * p0;
                    stage[(d + 1) * 132 + c]     = acc[mt][nt][1] * p0;
                    stage[d * 132 + c + 8]       = acc[mt][nt][2] * p1;
                    stage[(d + 1) * 132 + c + 8] = acc[mt][nt][3] * p1;
                }
            }
        }
        __syncthreads();
#pragma unroll
        for (int j = 0; j < 8; j++) {
            int idx = tid + j * 256;
            int d = idx >> 5, c4 = (idx & 31) * 4;
            float4 v = *(const float4*)&stage[d * 132 + c4];
            v.x = rna(v.x); v.y = rna(v.y); v.z = rna(v.z); v.w = rna(v.w);
            *(float4*)&g_M[((size_t)b * DIN + d0 + h * 64 + d) * H1n + c0 + c4] = v;
        }
        __syncthreads();
    }
}

// ---------------------------------------------------------------
// GEMME: D[d,t] = sum_c M[b,d,c]*Y[b,t,c]; out = D + bias2 + residual
// grid (DIN/128, T/128, B); M-dim = d, N-dim = t
// ---------------------------------------------------------------
__global__ void __launch_bounds__(256, 2)
k_mmE(const float* __restrict__ inp, float* __restrict__ out) {
    extern __shared__ __align__(16) char smem[];
    uint32_t sb = smem_to_u32(smem);
    const uint32_t* W = (const uint32_t*)smem;
    int tid = threadIdx.x;
    int b = blockIdx.z, d0 = blockIdx.x * 128, t0 = blockIdx.y * 128;
    float acc[4][4][4];
    gemm_main(W, sb,
              g_M + ((size_t)b * DIN + d0) * H1n, H1n,
              g_Y + ((size_t)b * Tn + t0) * H1n, H1n,
              H1n / 32, acc, tid);
    int wid = tid >> 5, lane = tid & 31, wm = wid & 1, wn = wid >> 1;
    int g = lane >> 2, tig = lane & 3;
    float* stage = (float*)smem;                        // [64][132] (rows = t)
    for (int h = 0; h < 2; h++) {
        if ((wn >> 1) == h) {
            int tl0 = (wn & 1) * 32;
#pragma unroll
            for (int mt = 0; mt < 4; mt++) {
                int d = wm * 64 + mt * 16 + g;
                float b0 = g_bias2[b * DIN + d0 + d], b1 = g_bias2[b * DIN + d0 + d + 8];
#pragma unroll
                for (int nt = 0; nt < 4; nt++) {
                    int t = tl0 + nt * 8 + tig * 2;
                    stage[t * 132 + d]           = acc[mt][nt][0] + b0;
                    stage[(t + 1) * 132 + d]     = acc[mt][nt][1] + b0;
                    stage[t * 132 + d + 8]       = acc[mt][nt][2] + b1;
                    stage[(t + 1) * 132 + d + 8] = acc[mt][nt][3] + b1;
                }
            }
        }
        __syncthreads();
#pragma unroll
        for (int j = 0; j < 8; j++) {
            int idx = tid + j * 256;
            int t = idx >> 5, c4 = (idx & 31) * 4;
            float4 v = *(const float4*)&stage[t * 132 + c4];
            size_t a = ((size_t)b * Tn + t0 + h * 64 + t) * DIN + d0 + c4;
            float4 r = *(const float4*)&inp[a];
            v.x += r.x; v.y += r.y; v.z += r.z; v.w += r.w;
            *(float4*)&out[a] = v;
        }
        __syncthreads();
    }
}

// ---------------------------------------------------------------
// prepass kernels: rna-to-tf32 rounding
// ---------------------------------------------------------------
__global__ void k_rnd_inp(const float* __restrict__ s) {
    size_t i = (size_t)blockIdx.x * 256 + threadIdx.x;
    float4 v = ((const float4*)s)[i];
    v.x = rna(v.x); v.y = rna(v.y); v.z = rna(v.z); v.w = rna(v.w);
    ((float4*)g_ir)[i] = v;
}
__global__ void k_rnd_w1(const float* __restrict__ s) {
    size_t i = (size_t)blockIdx.x * 256 + threadIdx.x;
    float4 v = ((const float4*)s)[i];
    v.x = rna(v.x); v.y = rna(v.y); v.z = rna(v.z); v.w = rna(v.w);
    ((float4*)g_w1r)[i] = v;
}
__global__ void k_rnd_pw(const float* __restrict__ s) {
    size_t i = (size_t)blockIdx.x * 256 + threadIdx.x;
    float4 v = ((const float4*)s)[i];
    v.x = rna(v.x); v.y = rna(v.y); v.z = rna(v.z); v.w = rna(v.w);
    ((float4*)g_pwr)[i] = v;
}
// w2s[b][d][o] = rna(w2[d,o] * pinv[b,o]);  grid (384, Bn)
__global__ void k_w2s(const float* __restrict__ w2w) {
    int b = blockIdx.y;
    size_t li = (size_t)blockIdx.x * 256 + threadIdx.x;   // over DIN*H2n/4
    size_t i4 = li * 4;
    int o = (int)(i4 & (H2n - 1));
    int d = (int)(i4 >> 10);
    float4 v = *(const float4*)&w2w[(size_t)d * H2n + o];
    float4 sc = *(const float4*)&g_pinv[b * H2n + o];
    float4 r;
    r.x = rna(v.x * sc.x); r.y = rna(v.y * sc.y);
    r.z = rna(v.z * sc.z); r.w = rna(v.w * sc.w);
    *(float4*)&g_w2s[((size_t)b * DIN + d) * H2n + o] = r;
}

// ---------------------------------------------------------------
// normalized depthwise weights
// ---------------------------------------------------------------
__global__ void k_dwn(const float* __restrict__ dw, const float* __restrict__ dg) {
    int b = blockIdx.x;
    __shared__ float red[256];
    __shared__ float nrm[KW];
    int tid = threadIdx.x;
    float acc[KW];
#pragma unroll
    for (int k = 0; k < KW; k++) acc[k] = 0.f;
    for (int c = tid; c < H1n; c += 256) {
        const float* p = dw + ((size_t)b * H1n + c) * KW;
#pragma unroll
        for (int k = 0; k < KW; k++) { float v = p[k]; acc[k] += v * v; }
    }
    for (int k = 0; k < KW; k++) {
        red[tid] = acc[k];
        __syncthreads();
        for (int s = 128; s > 0; s >>= 1) {
            if (tid < s) red[tid] += red[tid + s];
            __syncthreads();
        }
        if (tid == 0) nrm[k] = fmaxf(sqrtf(red[0]), 1e-12f);
        __syncthreads();
    }
    for (int c = tid; c < H1n; c += 256) {
        float g = dg[b * H1n + c];
        const float* p = dw + ((size_t)b * H1n + c) * KW;
        float* q = g_dwn + ((size_t)b * H1n + c) * KW;
#pragma unroll
        for (int k = 0; k < KW; k++) q[k] = p[k] / nrm[k] * g;
    }
}

// ---------------------------------------------------------------
// g_pinv[b,o] = 1/||p_w[b,:,o]||   (from ORIGINAL pw)
// ---------------------------------------------------------------
__global__ void k_pinv(const float* __restrict__ pw) {
    int b = blockIdx.y;
    int o = blockIdx.x * 256 + threadIdx.x;
    const float* base = pw + (size_t)b * H1n * H2n + o;
    float acc = 0.f;
#pragma unroll 8
    for (int c = 0; c < H1n; c++) {
        float v = base[(size_t)c * H2n];
        acc += v * v;
    }
    g_pinv[b * H2n + o] = 1.0f / fmaxf(sqrtf(acc), 1e-12f);
}

// ---------------------------------------------------------------
// depthwise conv [t][c]: Y = rna(T * conv(X))
// grid (T/256, H1/32, B), 256 thr
// ---------------------------------------------------------------
__global__ void k_conv() {
    int b = blockIdx.z, c0 = blockIdx.y * 32, t0 = blockIdx.x * 256;
    __shared__ float xs[264][32];
    int tid = threadIdx.x;
    int c = tid & 31, tr = tid >> 5;
    const float* X = g_X + (size_t)b * Tn * H1n + c0;
    for (int i = tr; i < 264; i += 8) {
        int t = t0 + i - 4;
        xs[i][c] = (t >= 0 && t < Tn) ? X[(size_t)t * H1n + c] : 0.f;
    }
    float w[KW];
    const float* wp = g_dwn + ((size_t)b * H1n + c0 + c) * KW;
#pragma unroll
    for (int k = 0; k < KW; k++) w[k] = wp[k];
    __syncthreads();
    size_t ybase = ((size_t)b * Tn + t0) * H1n + c0;
    for (int j = 0; j < 32; j++) {
        int t = tr * 32 + j;
        float s = 0.f;
#pragma unroll
        for (int k = 0; k < KW; k++) s += xs[t + k][c] * w[k];
        g_Y[ybase + (size_t)t * H1n + c] = rna(s * (float)Tn);
    }
}

// ---------------------------------------------------------------
// bias2[b,d] = sum_c M[b,d,c]*d_b[b,c] + sum_o w2[d,o]*p_b[b,o] + w2b[d]
// ---------------------------------------------------------------
__global__ void k_bias2(const float* __restrict__ db, const float* __restrict__ w2w,
                        const float* __restrict__ pb, const float* __restrict__ w2b) {
    int d = blockIdx.x, b = blockIdx.y;
    int tid = threadIdx.x;
    const float* Mrow = g_M + ((size_t)b * DIN + d) * H1n;
    const float* dbp = db + b * H1n;
    float acc = 0.f;
    for (int c = tid; c < H1n; c += 256) acc += Mrow[c] * dbp[c];
    const float* w2r = w2w + (size_t)d * H2n;
    const float* pbp = pb + b * H2n;
    for (int o = tid; o < H2n; o += 256) acc += w2r[o] * pbp[o];
    __shared__ float red[256];
    red[tid] = acc;
    __syncthreads();
    for (int s = 128; s > 0; s >>= 1) {
        if (tid < s) red[tid] += red[tid + s];
        __syncthreads();
    }
    if (tid == 0) g_bias2[b * DIN + d] = red[0] + w2b[d];
}

// ---------------------------------------------------------------
extern "C" void kernel_launch(void* const* d_in, const int* in_sizes, int n_in,
                              void* d_out, int out_size) {
    const float* inp = (const float*)d_in[0];   // [B,T,DIN]
    const float* dw  = (const float*)d_in[1];   // [B,H1,1,K]
    const float* dg  = (const float*)d_in[2];   // [B,H1]
    const float* db  = (const float*)d_in[3];   // [B,H1]
    const float* pw  = (const float*)d_in[4];   // [B,H1,H2,1]
    const float* pg  = (const float*)d_in[5];   // [B,H1]
    const float* pb  = (const float*)d_in[6];   // [B,H2]
    const float* w1w = (const float*)d_in[7];   // [H1,DIN]
    const float* w1b = (const float*)d_in[8];   // [H1]
    const float* w2w = (const float*)d_in[9];   // [DIN,H2]
    const float* w2b = (const float*)d_in[10];  // [DIN]
    float* out = (float*)d_out;                 // [B,T,DIN]
    (void)in_sizes; (void)n_in; (void)out_size;

    cudaFuncSetAttribute(k_mm1, cudaFuncAttributeMaxDynamicSharedMemorySize, GSMEM_B);
    cudaFuncSetAttribute(k_mmC, cudaFuncAttributeMaxDynamicSharedMemorySize, GSMEM_B);
    cudaFuncSetAttribute(k_mmE, cudaFuncAttributeMaxDynamicSharedMemorySize, GSMEM_B);

    k_dwn<<<Bn, 256>>>(dw, dg);
    k_pinv<<<dim3(H2n / 256, Bn), 256>>>(pw);

    unsigned nb_inp = (unsigned)((size_t)Bn * Tn * DIN / 4 / 256);   // 6144
    unsigned nb_w1  = (unsigned)((size_t)H1n * DIN / 4 / 256);       // 384
    unsigned nb_pw  = (unsigned)((size_t)Bn * H1n * H2n / 4 / 256);  // 16384
    unsigned nb_w2s = (unsigned)((size_t)DIN * H2n / 4 / 256);       // 384
    k_rnd_inp<<<nb_inp, 256>>>(inp);
    k_rnd_w1<<<nb_w1, 256>>>(w1w);
    k_rnd_pw<<<nb_pw, 256>>>(pw);
    k_w2s<<<dim3(nb_w2s, Bn), 256>>>(w2w);

    k_mm1<<<dim3(H1n / 128, Tn / 128, Bn), 256, GSMEM_B>>>(w1b);
    k_conv<<<dim3(Tn / 256, H1n / 32, Bn), 256>>>();
    k_mmC<<<dim3(H1n / 128, DIN / 128, Bn), 256, GSMEM_B>>>(pg);
    k_bias2<<<dim3(DIN, Bn), 256>>>(db, w2w, pb, w2b);
    k_mmE<<<dim3(DIN / 128, Tn / 128, Bn), 256, GSMEM_B>>>(inp, out);
}